// round 4
// baseline (speedup 1.0000x reference)
#include <cuda_runtime.h>
#include <cuda_bf16.h>
#include <math.h>
#include <stdint.h>

// ---------------- problem constants ----------------
#define B 128
#define S_SRC 128
#define S_TRG 64
#define H 1024

#define KE 1024      // enc recurrent K
#define KDR 1344     // dec recurrent K padded (real 1324 = 1024 h + 300 ctx)
#define KSE 320      // src embed K padded (real 300)
#define KAE 576      // ans embed K padded (real 556)

#define SMEMB 92160  // dynamic smem bytes for mma_gemm

// ---------------- bf16 hi/lo weights (converted once per launch) ----------------
__device__ __nv_bfloat16 g_WerH[4096 * KE],  g_WerL[4096 * KE];     // enc recurrent, packed-n
__device__ __nv_bfloat16 g_WdrH[4096 * KDR], g_WdrL[4096 * KDR];    // dec recurrent, packed-n
__device__ __nv_bfloat16 g_WeiH[4096 * KSE], g_WeiL[4096 * KSE];    // enc input, packed-n
__device__ __nv_bfloat16 g_WdiH[4096 * KAE], g_WdiL[4096 * KAE];    // dec input, packed-n
__device__ __nv_bfloat16 g_WqkH[128 * 1024], g_WqkL[128 * 1024];
__device__ __nv_bfloat16 g_WqvH[320 * 1024], g_WqvL[320 * 1024];
__device__ __nv_bfloat16 g_WaH[128 * 1024],  g_WaL[128 * 1024];
__device__ __nv_bfloat16 g_Wh1H[2048 * 1024], g_Wh1L[2048 * 1024];
__device__ __nv_bfloat16 g_Wh2H[1024 * 2048], g_Wh2L[1024 * 2048];
__device__ __nv_bfloat16 g_Wc1H[2048 * 1024], g_Wc1L[2048 * 1024];
__device__ __nv_bfloat16 g_Wc2H[1024 * 2048], g_Wc2L[1024 * 2048];

// ---------------- activations ----------------
__device__ __nv_bfloat16 g_seH[(size_t)S_SRC * B * KSE], g_seL[(size_t)S_SRC * B * KSE];
__device__ __nv_bfloat16 g_aeH[(size_t)S_TRG * B * KAE], g_aeL[(size_t)S_TRG * B * KAE];
__device__ float g_encpre[(size_t)S_SRC * B * 4096];
__device__ float g_decpre[(size_t)S_TRG * B * 4096];
__device__ __nv_bfloat16 g_shH[(size_t)B * S_SRC * H], g_shL[(size_t)B * S_SRC * H];
__device__ float g_qkey[(size_t)B * S_SRC * 112];
__device__ float g_qval[(size_t)B * S_SRC * 304];
__device__ __nv_bfloat16 g_ehH[2 * B * H], g_ehL[2 * B * H];
__device__ __nv_bfloat16 g_dAH[2 * B * KDR], g_dAL[2 * B * KDR];
__device__ float g_ec[B * H], g_dc[B * H];
__device__ __nv_bfloat16 g_ecH[B * H], g_ecL[B * H];
__device__ __nv_bfloat16 g_t1H[B * 2048], g_t1L[B * 2048];
__device__ float g_akey[B * 112];

// ---------------- weight conversion (fp32 -> bf16 hi/lo, padded layouts) ----------------
// mode 0: plain [Nreal][lds] row-major (zero-pad N/K)
// mode 1: packed-n: orig = (n&3)*1024 + (n>>2); src1[orig*lds + k] for k < Kreal
// mode 2: dec recurrent packed: k<1024 -> Whh[orig*1024+k]; k<1324 -> Wih[orig*856+556+(k-1024)]
__global__ void convw_kernel(__nv_bfloat16* dh, __nv_bfloat16* dl,
                             const float* __restrict__ s1, const float* __restrict__ s2,
                             int Npad, int Nreal, int Kpad, int Kreal, int lds, int mode) {
    int64_t tot = (int64_t)Npad * Kpad;
    int64_t stride = (int64_t)gridDim.x * blockDim.x;
    for (int64_t i = (int64_t)blockIdx.x * blockDim.x + threadIdx.x; i < tot; i += stride) {
        int n = (int)(i / Kpad), k = (int)(i % Kpad);
        float v = 0.f;
        if (mode == 0) {
            if (n < Nreal && k < Kreal) v = s1[(int64_t)n * lds + k];
        } else {
            int orig = (n & 3) * 1024 + (n >> 2);
            if (mode == 1) { if (k < Kreal) v = s1[(int64_t)orig * lds + k]; }
            else {
                if (k < 1024) v = s1[(int64_t)orig * 1024 + k];
                else if (k < 1324) v = s2[(int64_t)orig * 856 + 556 + (k - 1024)];
            }
        }
        __nv_bfloat16 hv = __float2bfloat16(v);
        dh[i] = hv;
        dl[i] = __float2bfloat16(v - __bfloat162float(hv));
    }
}

// ---------------- gather embeddings (bf16 hi/lo) + zero states ----------------
__global__ void gather_kernel(const int* __restrict__ src_seqs, const int* __restrict__ trg_nt,
                              const int* __restrict__ par_nt, const int* __restrict__ par_lex,
                              const float* __restrict__ lex_emb, const float* __restrict__ nt_emb) {
    const int64_t nse = (int64_t)S_SRC * B * KSE;   // 5.24M
    const int64_t nae = (int64_t)S_TRG * B * KAE;   // 4.72M
    int64_t stride = (int64_t)gridDim.x * blockDim.x;
    for (int64_t i = (int64_t)blockIdx.x * blockDim.x + threadIdx.x; i < nse; i += stride) {
        {
            int d = (int)(i % KSE);
            int r = (int)(i / KSE);
            int s = r >> 7, b = r & 127;
            float v = (d < 300) ? lex_emb[(int64_t)src_seqs[b * S_SRC + s] * 300 + d] : 0.f;
            __nv_bfloat16 hv = __float2bfloat16(v);
            g_seH[i] = hv;
            g_seL[i] = __float2bfloat16(v - __bfloat162float(hv));
        }
        if (i < nae) {
            int d = (int)(i % KAE);
            int r = (int)(i / KAE);
            int t = r >> 7, b = r & 127;
            float v = 0.f;
            if (d < 128)      v = nt_emb[(int64_t)trg_nt[b * S_TRG + t] * 128 + d];
            else if (d < 256) v = nt_emb[(int64_t)par_nt[b * S_TRG + t] * 128 + (d - 128)];
            else if (d < 556) v = lex_emb[(int64_t)par_lex[b * S_TRG + t] * 300 + (d - 256)];
            __nv_bfloat16 hv = __float2bfloat16(v);
            g_aeH[i] = hv;
            g_aeL[i] = __float2bfloat16(v - __bfloat162float(hv));
        }
        if (i < 2 * B * KDR) { g_dAH[i] = __float2bfloat16(0.f); g_dAL[i] = __float2bfloat16(0.f); }
        if (i < 2 * B * H)   { g_ehH[i] = __float2bfloat16(0.f); g_ehL[i] = __float2bfloat16(0.f); }
        if (i < B * H)       g_ec[i] = 0.f;
    }
}

// ---------------- mma helpers ----------------
__device__ __forceinline__ void ldmx4(uint32_t addr, uint32_t* r) {
    asm volatile("ldmatrix.sync.aligned.m8n8.x4.shared.b16 {%0,%1,%2,%3}, [%4];"
                 : "=r"(r[0]), "=r"(r[1]), "=r"(r[2]), "=r"(r[3]) : "r"(addr));
}
__device__ __forceinline__ void ldmx2(uint32_t addr, uint32_t* r) {
    asm volatile("ldmatrix.sync.aligned.m8n8.x2.shared.b16 {%0,%1}, [%2];"
                 : "=r"(r[0]), "=r"(r[1]) : "r"(addr));
}
__device__ __forceinline__ void mma16816(float* c, const uint32_t* a, const uint32_t* b) {
    asm volatile("mma.sync.aligned.m16n8k16.row.col.f32.bf16.bf16.f32 "
                 "{%0,%1,%2,%3},{%4,%5,%6,%7},{%8,%9},{%0,%1,%2,%3};"
                 : "+f"(c[0]), "+f"(c[1]), "+f"(c[2]), "+f"(c[3])
                 : "r"(a[0]), "r"(a[1]), "r"(a[2]), "r"(a[3]), "r"(b[0]), "r"(b[1]));
}
__device__ __forceinline__ void cpa16(uint32_t dst, const void* src) {
    asm volatile("cp.async.cg.shared.global [%0], [%1], 16;" :: "r"(dst), "l"(src));
}

// smem layout (bf16 elems): A[buf][hl][128][72] then W[buf][hl][32][72] at elem 36864
__device__ __forceinline__ void load_chunk(uint32_t smb, int buf, int t, int k0,
    const __nv_bfloat16* __restrict__ Ah, const __nv_bfloat16* __restrict__ Al, int ldA, int mbase,
    const __nv_bfloat16* __restrict__ Wh, const __nv_bfloat16* __restrict__ Wl, int ldW, int nbase)
{
#pragma unroll
    for (int i = 0; i < 8; i++) {
        int u = i * 256 + t;
        int hl = u >> 10;
        int rem = u & 1023;
        int row = rem >> 3, grp = rem & 7;
        const __nv_bfloat16* src = (hl ? Al : Ah) + (int64_t)(mbase + row) * ldA + k0 + grp * 8;
        uint32_t dst = smb + (uint32_t)(((buf * 2 + hl) * 128 + row) * 72 + grp * 8) * 2u;
        cpa16(dst, src);
    }
#pragma unroll
    for (int i = 0; i < 2; i++) {
        int u = i * 256 + t;
        int hl = u >> 8;
        int rem = u & 255;
        int row = rem >> 3, grp = rem & 7;
        const __nv_bfloat16* src = (hl ? Wl : Wh) + (int64_t)(nbase + row) * ldW + k0 + grp * 8;
        uint32_t dst = smb + (uint32_t)(36864 + ((buf * 2 + hl) * 32 + row) * 72 + grp * 8) * 2u;
        cpa16(dst, src);
    }
    asm volatile("cp.async.commit_group;" ::: "memory");
}

// ---------------- unified pipelined bf16-split tensor-core GEMM ----------------
// Tile: M=128 per grid.y block, N=32 per grid.x block, K chunks of 64, double-buffered.
// OUT: 0 fp32 store (+ACT), 1 bf16 hi/lo store (+ACT), 2 encoder LSTM epi, 3 decoder LSTM epi
template<int OUT, int ACT>
__global__ __launch_bounds__(256) void mma_gemm(
    const __nv_bfloat16* __restrict__ Ah, const __nv_bfloat16* __restrict__ Al, int ldA,
    const __nv_bfloat16* __restrict__ Wh, const __nv_bfloat16* __restrict__ Wl, int ldW,
    int N, int KT,
    const float* __restrict__ bias, const float* __restrict__ add,
    float* __restrict__ Cf, __nv_bfloat16* __restrict__ Ch, __nv_bfloat16* __restrict__ Cl, int ldC,
    const int* __restrict__ lens, int s,
    __nv_bfloat16* __restrict__ houtH, __nv_bfloat16* __restrict__ houtL, int ldHo,
    float* __restrict__ cbuf,
    __nv_bfloat16* __restrict__ auxH, __nv_bfloat16* __restrict__ auxL,
    float* __restrict__ outF)
{
    extern __shared__ char smraw[];
    uint32_t smb = (uint32_t)__cvta_generic_to_shared(smraw);
    const int t = threadIdx.x;
    const int lane = t & 31, w = t >> 5;
    const int wm = w & 3, wn = w >> 2;            // 4 m-subtiles x 2 n-subtiles
    const int mbase = blockIdx.y * 128;
    const int nbase = blockIdx.x * 32;

    float acc[2][2][4];
#pragma unroll
    for (int a = 0; a < 2; a++)
#pragma unroll
        for (int b2 = 0; b2 < 2; b2++)
#pragma unroll
            for (int r = 0; r < 4; r++) acc[a][b2][r] = 0.f;

    load_chunk(smb, 0, t, 0, Ah, Al, ldA, mbase, Wh, Wl, ldW, nbase);

    for (int kc = 0; kc < KT; kc++) {
        const int cur = kc & 1;
        if (kc + 1 < KT) {
            load_chunk(smb, cur ^ 1, t, (kc + 1) * 64, Ah, Al, ldA, mbase, Wh, Wl, ldW, nbase);
            asm volatile("cp.async.wait_group 1;" ::: "memory");
        } else {
            asm volatile("cp.async.wait_group 0;" ::: "memory");
        }
        __syncthreads();
#pragma unroll
        for (int kk16 = 0; kk16 < 64; kk16 += 16) {
            uint32_t bh[2][2], bl[2][2];
#pragma unroll
            for (int nf = 0; nf < 2; nf++) {
                int rowW = wn * 16 + nf * 8 + (lane & 7);
                int kcol = kk16 + ((lane >> 3) & 1) * 8;
                ldmx2(smb + (uint32_t)(36864 + ((cur * 2 + 0) * 32 + rowW) * 72 + kcol) * 2u, bh[nf]);
                ldmx2(smb + (uint32_t)(36864 + ((cur * 2 + 1) * 32 + rowW) * 72 + kcol) * 2u, bl[nf]);
            }
#pragma unroll
            for (int mf = 0; mf < 2; mf++) {
                int rowA = wm * 32 + mf * 16 + (lane & 7) + ((lane >> 3) & 1) * 8;
                int kcol = kk16 + ((lane >> 4) & 1) * 8;
                uint32_t ah[4], al[4];
                ldmx4(smb + (uint32_t)(((cur * 2 + 0) * 128 + rowA) * 72 + kcol) * 2u, ah);
                ldmx4(smb + (uint32_t)(((cur * 2 + 1) * 128 + rowA) * 72 + kcol) * 2u, al);
#pragma unroll
                for (int nf = 0; nf < 2; nf++) {
                    mma16816(acc[mf][nf], ah, bh[nf]);
                    mma16816(acc[mf][nf], al, bh[nf]);
                    mma16816(acc[mf][nf], ah, bl[nf]);
                }
            }
        }
        __syncthreads();
    }

    const int g2 = lane >> 2, q2 = (lane & 3) * 2;

    if (OUT <= 1) {
#pragma unroll
        for (int mf = 0; mf < 2; mf++)
#pragma unroll
            for (int nf = 0; nf < 2; nf++)
#pragma unroll
                for (int r = 0; r < 4; r++) {
                    int row = mbase + wm * 32 + mf * 16 + g2 + (r >> 1) * 8;
                    int col = nbase + wn * 16 + nf * 8 + q2 + (r & 1);
                    if (col < N) {
                        float v = acc[mf][nf][r];
                        if (bias) v += bias[col];
                        if (ACT == 1) v = fmaxf(v, 0.f);
                        if (ACT == 2) v = tanhf(v);
                        if (OUT == 0) Cf[(int64_t)row * ldC + col] = v;
                        else {
                            __nv_bfloat16 hv = __float2bfloat16(v);
                            Ch[(int64_t)row * ldC + col] = hv;
                            Cl[(int64_t)row * ldC + col] = __float2bfloat16(v - __bfloat162float(hv));
                        }
                    }
                }
        return;
    }

    // ---- fused LSTM epilogue (M=128, gridDim.y==1, packed-n: col = j*4+gate) ----
    float* zb = (float*)smraw;   // [128][33]
    __syncthreads();
#pragma unroll
    for (int mf = 0; mf < 2; mf++)
#pragma unroll
        for (int nf = 0; nf < 2; nf++)
#pragma unroll
            for (int r = 0; r < 4; r++) {
                int row = wm * 32 + mf * 16 + g2 + (r >> 1) * 8;
                int col = wn * 16 + nf * 8 + q2 + (r & 1);
                zb[row * 33 + col] = acc[mf][nf][r];
            }
    __syncthreads();

    const int b = t & 127;
    const int jj0 = (t >> 7) * 4;
#pragma unroll
    for (int jj = jj0; jj < jj0 + 4; jj++) {
        const int jglob = (nbase >> 2) + jj;
        float4 pre = *(const float4*)&add[(int64_t)b * 4096 + nbase + jj * 4];
        float zi = zb[b * 33 + jj * 4 + 0] + pre.x + bias[jglob];
        float zf = zb[b * 33 + jj * 4 + 1] + pre.y + bias[1024 + jglob];
        float zg = zb[b * 33 + jj * 4 + 2] + pre.z + bias[2048 + jglob];
        float zo = zb[b * 33 + jj * 4 + 3] + pre.w + bias[3072 + jglob];
        float cold = cbuf[b * H + jglob];
        float si = 1.f / (1.f + expf(-zi));
        float sf = 1.f / (1.f + expf(-zf));
        float so = 1.f / (1.f + expf(-zo));
        float c2 = sf * cold + si * tanhf(zg);
        float h2 = so * tanhf(c2);
        __nv_bfloat16 nh = __float2bfloat16(h2);
        __nv_bfloat16 nl = __float2bfloat16(h2 - __bfloat162float(nh));
        if (OUT == 2) {
            bool valid = s < lens[b];
            if (valid) cbuf[b * H + jglob] = c2;
            houtH[(int64_t)b * ldHo + jglob] = valid ? nh : Ah[(int64_t)b * ldA + jglob];
            houtL[(int64_t)b * ldHo + jglob] = valid ? nl : Al[(int64_t)b * ldA + jglob];
            __nv_bfloat16 z16 = __float2bfloat16(0.f);
            auxH[((int64_t)b * S_SRC + s) * H + jglob] = valid ? nh : z16;
            auxL[((int64_t)b * S_SRC + s) * H + jglob] = valid ? nl : z16;
        } else {
            cbuf[b * H + jglob] = c2;
            houtH[(int64_t)b * ldHo + jglob] = nh;
            houtL[(int64_t)b * ldHo + jglob] = nl;
            outF[((int64_t)b * S_TRG + s) * H + jglob] = h2;
        }
    }
}

// ---------------- attention stage 2: softmax + context ----------------
__global__ __launch_bounds__(128) void attn2_kernel(const int* __restrict__ lens,
                                                    __nv_bfloat16* __restrict__ ctxH,
                                                    __nv_bfloat16* __restrict__ ctxL) {
    __shared__ float ak[112];
    __shared__ float en[128];
    __shared__ float red[8];
    int b = blockIdx.x;
    int tid = threadIdx.x;
    int lane = tid & 31, wid = tid >> 5;

    if (tid < 100) ak[tid] = g_akey[b * 112 + tid];
    __syncthreads();

    int L = lens[b];
    float e;
    {
        const float* qk = &g_qkey[((int64_t)b * S_SRC + tid) * 112];
        float p = 0.f;
#pragma unroll 4
        for (int d = 0; d < 100; d++) p = fmaf(qk[d], ak[d], p);
        e = (tid < L) ? p : -1e9f;
    }
    float mx = e;
    for (int o = 16; o; o >>= 1) mx = fmaxf(mx, __shfl_xor_sync(0xffffffffu, mx, o));
    if (lane == 0) red[wid] = mx;
    __syncthreads();
    mx = fmaxf(fmaxf(red[0], red[1]), fmaxf(red[2], red[3]));
    float ex = expf(e - mx);
    float sm = ex;
    for (int o = 16; o; o >>= 1) sm += __shfl_xor_sync(0xffffffffu, sm, o);
    if (lane == 0) red[4 + wid] = sm;
    __syncthreads();
    sm = red[4] + red[5] + red[6] + red[7];
    en[tid] = ex / sm;
    __syncthreads();

    for (int d = tid; d < 300; d += 128) {
        float c = 0.f;
#pragma unroll 4
        for (int s2 = 0; s2 < S_SRC; s2++)
            c = fmaf(en[s2], g_qval[((int64_t)b * S_SRC + s2) * 304 + d], c);
        __nv_bfloat16 hv = __float2bfloat16(c);
        ctxH[(int64_t)b * KDR + 1024 + d] = hv;
        ctxL[(int64_t)b * KDR + 1024 + d] = __float2bfloat16(c - __bfloat162float(hv));
    }
}

// ---------------- launcher ----------------
extern "C" void kernel_launch(void* const* d_in, const int* in_sizes, int n_in,
                              void* d_out, int out_size) {
    const int*   src_seqs = (const int*)d_in[0];
    const int*   src_len  = (const int*)d_in[1];
    const int*   trg_nt   = (const int*)d_in[2];
    const int*   par_nt   = (const int*)d_in[3];
    const int*   par_lex  = (const int*)d_in[4];
    const float* lex_emb  = (const float*)d_in[5];
    const float* nt_emb   = (const float*)d_in[6];
    const float* enc_Wih  = (const float*)d_in[7];
    const float* enc_Whh  = (const float*)d_in[8];
    const float* enc_b    = (const float*)d_in[9];
    const float* dec_Wih  = (const float*)d_in[10];
    const float* dec_Whh  = (const float*)d_in[11];
    const float* dec_b    = (const float*)d_in[12];
    const float* Wh1 = (const float*)d_in[13];
    const float* bh1 = (const float*)d_in[14];
    const float* Wh2 = (const float*)d_in[15];
    const float* bh2 = (const float*)d_in[16];
    const float* Wc1 = (const float*)d_in[17];
    const float* bc1 = (const float*)d_in[18];
    const float* Wc2 = (const float*)d_in[19];
    const float* bc2 = (const float*)d_in[20];
    const float* Wa  = (const float*)d_in[21];
    const float* ba  = (const float*)d_in[22];
    const float* Wqk = (const float*)d_in[23];
    const float* bqk = (const float*)d_in[24];
    const float* Wqv = (const float*)d_in[25];
    const float* bqv = (const float*)d_in[26];
    float* out = (float*)d_out;

    // opt-in to >48KB dynamic smem (idempotent)
    cudaFuncSetAttribute(mma_gemm<0,0>, cudaFuncAttributeMaxDynamicSharedMemorySize, SMEMB);
    cudaFuncSetAttribute(mma_gemm<0,2>, cudaFuncAttributeMaxDynamicSharedMemorySize, SMEMB);
    cudaFuncSetAttribute(mma_gemm<1,0>, cudaFuncAttributeMaxDynamicSharedMemorySize, SMEMB);
    cudaFuncSetAttribute(mma_gemm<1,1>, cudaFuncAttributeMaxDynamicSharedMemorySize, SMEMB);
    cudaFuncSetAttribute(mma_gemm<2,0>, cudaFuncAttributeMaxDynamicSharedMemorySize, SMEMB);
    cudaFuncSetAttribute(mma_gemm<3,0>, cudaFuncAttributeMaxDynamicSharedMemorySize, SMEMB);

    // device-global pointers
    __nv_bfloat16 *WerH,*WerL,*WdrH,*WdrL,*WeiH,*WeiL,*WdiH,*WdiL;
    __nv_bfloat16 *WqkH,*WqkL,*WqvH,*WqvL,*WaH,*WaL;
    __nv_bfloat16 *Wh1H,*Wh1L,*Wh2H,*Wh2L,*Wc1H,*Wc1L,*Wc2H,*Wc2L;
    __nv_bfloat16 *seH,*seL,*aeH,*aeL,*shH,*shL,*ehH,*ehL,*dAH,*dAL,*ecH,*ecL,*t1H,*t1L;
    float *encpre,*decpre,*qkey,*qval,*ec,*dc,*akey;
    cudaGetSymbolAddress((void**)&WerH, g_WerH); cudaGetSymbolAddress((void**)&WerL, g_WerL);
    cudaGetSymbolAddress((void**)&WdrH, g_WdrH); cudaGetSymbolAddress((void**)&WdrL, g_WdrL);
    cudaGetSymbolAddress((void**)&WeiH, g_WeiH); cudaGetSymbolAddress((void**)&WeiL, g_WeiL);
    cudaGetSymbolAddress((void**)&WdiH, g_WdiH); cudaGetSymbolAddress((void**)&WdiL, g_WdiL);
    cudaGetSymbolAddress((void**)&WqkH, g_WqkH); cudaGetSymbolAddress((void**)&WqkL, g_WqkL);
    cudaGetSymbolAddress((void**)&WqvH, g_WqvH); cudaGetSymbolAddress((void**)&WqvL, g_WqvL);
    cudaGetSymbolAddress((void**)&WaH,  g_WaH ); cudaGetSymbolAddress((void**)&WaL,  g_WaL );
    cudaGetSymbolAddress((void**)&Wh1H, g_Wh1H); cudaGetSymbolAddress((void**)&Wh1L, g_Wh1L);
    cudaGetSymbolAddress((void**)&Wh2H, g_Wh2H); cudaGetSymbolAddress((void**)&Wh2L, g_Wh2L);
    cudaGetSymbolAddress((void**)&Wc1H, g_Wc1H); cudaGetSymbolAddress((void**)&Wc1L, g_Wc1L);
    cudaGetSymbolAddress((void**)&Wc2H, g_Wc2H); cudaGetSymbolAddress((void**)&Wc2L, g_Wc2L);
    cudaGetSymbolAddress((void**)&seH, g_seH); cudaGetSymbolAddress((void**)&seL, g_seL);
    cudaGetSymbolAddress((void**)&aeH, g_aeH); cudaGetSymbolAddress((void**)&aeL, g_aeL);
    cudaGetSymbolAddress((void**)&shH, g_shH); cudaGetSymbolAddress((void**)&shL, g_shL);
    cudaGetSymbolAddress((void**)&ehH, g_ehH); cudaGetSymbolAddress((void**)&ehL, g_ehL);
    cudaGetSymbolAddress((void**)&dAH, g_dAH); cudaGetSymbolAddress((void**)&dAL, g_dAL);
    cudaGetSymbolAddress((void**)&ecH, g_ecH); cudaGetSymbolAddress((void**)&ecL, g_ecL);
    cudaGetSymbolAddress((void**)&t1H, g_t1H); cudaGetSymbolAddress((void**)&t1L, g_t1L);
    cudaGetSymbolAddress((void**)&encpre, g_encpre); cudaGetSymbolAddress((void**)&decpre, g_decpre);
    cudaGetSymbolAddress((void**)&qkey, g_qkey); cudaGetSymbolAddress((void**)&qval, g_qval);
    cudaGetSymbolAddress((void**)&ec, g_ec); cudaGetSymbolAddress((void**)&dc, g_dc);
    cudaGetSymbolAddress((void**)&akey, g_akey);

    // ---- setup: weight conversions + gathers ----
    convw_kernel<<<1024, 256>>>(WerH, WerL, enc_Whh, nullptr, 4096, 0, KE, 1024, 1024, 1);
    convw_kernel<<<1024, 256>>>(WdrH, WdrL, dec_Whh, dec_Wih, 4096, 0, KDR, 1324, 0, 2);
    convw_kernel<<<1024, 256>>>(WeiH, WeiL, enc_Wih, nullptr, 4096, 0, KSE, 300, 300, 1);
    convw_kernel<<<1024, 256>>>(WdiH, WdiL, dec_Wih, nullptr, 4096, 0, KAE, 556, 856, 1);
    convw_kernel<<<256, 256>>>(WqkH, WqkL, Wqk, nullptr, 128, 100, 1024, 1024, 1024, 0);
    convw_kernel<<<256, 256>>>(WqvH, WqvL, Wqv, nullptr, 320, 300, 1024, 1024, 1024, 0);
    convw_kernel<<<256, 256>>>(WaH,  WaL,  Wa,  nullptr, 128, 100, 1024, 1024, 1024, 0);
    convw_kernel<<<1024, 256>>>(Wh1H, Wh1L, Wh1, nullptr, 2048, 2048, 1024, 1024, 1024, 0);
    convw_kernel<<<1024, 256>>>(Wh2H, Wh2L, Wh2, nullptr, 1024, 1024, 2048, 2048, 2048, 0);
    convw_kernel<<<1024, 256>>>(Wc1H, Wc1L, Wc1, nullptr, 2048, 2048, 1024, 1024, 1024, 0);
    convw_kernel<<<1024, 256>>>(Wc2H, Wc2L, Wc2, nullptr, 1024, 1024, 2048, 2048, 2048, 0);
    gather_kernel<<<2048, 256>>>(src_seqs, trg_nt, par_nt, par_lex, lex_emb, nt_emb);

    // ---- input-side precompute (packed-n fp32 outputs) ----
    mma_gemm<0,0><<<dim3(128,128), 256, SMEMB>>>(seH, seL, KSE, WeiH, WeiL, KSE, 4096, KSE/64,
        nullptr, nullptr, encpre, nullptr, nullptr, 4096,
        nullptr, 0, nullptr, nullptr, 0, nullptr, nullptr, nullptr, nullptr);
    mma_gemm<0,0><<<dim3(128,64), 256, SMEMB>>>(aeH, aeL, KAE, WdiH, WdiL, KAE, 4096, KAE/64,
        nullptr, nullptr, decpre, nullptr, nullptr, 4096,
        nullptr, 0, nullptr, nullptr, 0, nullptr, nullptr, nullptr, nullptr);

    // ---- encoder recurrence ----
    for (int s = 0; s < S_SRC; s++) {
        int p = s & 1;
        mma_gemm<2,0><<<dim3(128,1), 256, SMEMB>>>(ehH + p*B*H, ehL + p*B*H, H,
            WerH, WerL, KE, 4096, KE/64,
            enc_b, encpre + (int64_t)s*B*4096, nullptr, nullptr, nullptr, 0,
            src_len, s, ehH + (p^1)*B*H, ehL + (p^1)*B*H, H, ec, shH, shL, nullptr);
    }
    __nv_bfloat16* ehTH = ehH + (S_SRC & 1) * B * H;
    __nv_bfloat16* ehTL = ehL + (S_SRC & 1) * B * H;

    // ---- attention keys/values (batched over all positions) ----
    mma_gemm<0,2><<<dim3(4,128), 256, SMEMB>>>(shH, shL, H, WqkH, WqkL, 1024, 100, 16,
        bqk, nullptr, qkey, nullptr, nullptr, 112,
        nullptr, 0, nullptr, nullptr, 0, nullptr, nullptr, nullptr, nullptr);
    mma_gemm<0,0><<<dim3(10,128), 256, SMEMB>>>(shH, shL, H, WqvH, WqvL, 1024, 300, 16,
        bqv, nullptr, qval, nullptr, nullptr, 304,
        nullptr, 0, nullptr, nullptr, 0, nullptr, nullptr, nullptr, nullptr);

    // ---- decoder init MLPs ----
    convw_kernel<<<256, 256>>>(ecH, ecL, ec, nullptr, 128, 128, 1024, 1024, 1024, 0);
    mma_gemm<1,1><<<dim3(64,1), 256, SMEMB>>>(ehTH, ehTL, H, Wh1H, Wh1L, 1024, 2048, 16,
        bh1, nullptr, nullptr, t1H, t1L, 2048,
        nullptr, 0, nullptr, nullptr, 0, nullptr, nullptr, nullptr, nullptr);
    mma_gemm<1,0><<<dim3(32,1), 256, SMEMB>>>(t1H, t1L, 2048, Wh2H, Wh2L, 2048, 1024, 32,
        bh2, nullptr, nullptr, dAH, dAL, KDR,
        nullptr, 0, nullptr, nullptr, 0, nullptr, nullptr, nullptr, nullptr);
    mma_gemm<1,1><<<dim3(64,1), 256, SMEMB>>>(ecH, ecL, H, Wc1H, Wc1L, 1024, 2048, 16,
        bc1, nullptr, nullptr, t1H, t1L, 2048,
        nullptr, 0, nullptr, nullptr, 0, nullptr, nullptr, nullptr, nullptr);
    mma_gemm<0,0><<<dim3(32,1), 256, SMEMB>>>(t1H, t1L, 2048, Wc2H, Wc2L, 2048, 1024, 32,
        bc2, nullptr, dc, nullptr, nullptr, 1024,
        nullptr, 0, nullptr, nullptr, 0, nullptr, nullptr, nullptr, nullptr);

    // ---- decoder recurrence with attention ----
    for (int t = 0; t < S_TRG; t++) {
        int p = t & 1;
        mma_gemm<0,2><<<dim3(4,1), 256, SMEMB>>>(dAH + p*B*KDR, dAL + p*B*KDR, KDR,
            WaH, WaL, 1024, 100, 16,
            ba, nullptr, akey, nullptr, nullptr, 112,
            nullptr, 0, nullptr, nullptr, 0, nullptr, nullptr, nullptr, nullptr);
        attn2_kernel<<<128, 128>>>(src_len, dAH + p*B*KDR, dAL + p*B*KDR);
        mma_gemm<3,0><<<dim3(128,1), 256, SMEMB>>>(dAH + p*B*KDR, dAL + p*B*KDR, KDR,
            WdrH, WdrL, KDR, 4096, KDR/64,
            dec_b, decpre + (int64_t)t*B*4096, nullptr, nullptr, nullptr, 0,
            src_len, t, dAH + (p^1)*B*KDR, dAL + (p^1)*B*KDR, KDR, dc, nullptr, nullptr, out);
    }
}

// round 5
// speedup vs baseline: 1.0227x; 1.0227x over previous
#include <cuda_runtime.h>
#include <cuda_bf16.h>
#include <math.h>
#include <stdint.h>

#define B 128
#define S_SRC 128
#define S_TRG 64
#define H 1024
#define KE 1024
#define KDR 1344
#define KSE 320
#define KAE 576
#define ECH 16
#define DCH 21
#define STGB (288*72*2)
#define ENC_SMEM ((ECH*32*72 + 3*288*72)*2)
#define DEC_SMEM ((DCH*32*72 + 3*288*72)*2)
#define GEN_SMEM 92160

// ---------------- weights (bf16 hi/lo, converted once) ----------------
__device__ __nv_bfloat16 g_WerH[4096*KE],  g_WerL[4096*KE];
__device__ __nv_bfloat16 g_WdrH[4096*KDR], g_WdrL[4096*KDR];
__device__ __nv_bfloat16 g_WeiH[4096*KSE], g_WeiL[4096*KSE];
__device__ __nv_bfloat16 g_WdiH[4096*KAE], g_WdiL[4096*KAE];
__device__ __nv_bfloat16 g_WqkH[128*1024], g_WqkL[128*1024];
__device__ __nv_bfloat16 g_WqvH[320*1024], g_WqvL[320*1024];
__device__ __nv_bfloat16 g_WaH[128*1024],  g_WaL[128*1024];
__device__ __nv_bfloat16 g_Wh1H[2048*1024], g_Wh1L[2048*1024];
__device__ __nv_bfloat16 g_Wh2H[1024*2048], g_Wh2L[1024*2048];
__device__ __nv_bfloat16 g_Wc1H[2048*1024], g_Wc1L[2048*1024];
__device__ __nv_bfloat16 g_Wc2H[1024*2048], g_Wc2L[1024*2048];

// ---------------- activations / state ----------------
__device__ __nv_bfloat16 g_seH[(size_t)S_SRC*B*KSE], g_seL[(size_t)S_SRC*B*KSE];
__device__ __nv_bfloat16 g_aeH[(size_t)S_TRG*B*KAE], g_aeL[(size_t)S_TRG*B*KAE];
__device__ float g_encpre[(size_t)S_SRC*B*4096];
__device__ float g_decpre[(size_t)S_TRG*B*4096];
__device__ __nv_bfloat16 g_shH[(size_t)B*S_SRC*H], g_shL[(size_t)B*S_SRC*H];
__device__ float g_qkey[(size_t)B*S_SRC*112];
__device__ float g_qval[(size_t)B*S_SRC*304];
__device__ __nv_bfloat16 g_ehH[2*B*H], g_ehL[2*B*H];
__device__ __nv_bfloat16 g_dAH[2*B*KDR], g_dAL[2*B*KDR];
__device__ float g_ec[B*H], g_dc[B*H];
__device__ __nv_bfloat16 g_ecH[B*H], g_ecL[B*H];
__device__ __nv_bfloat16 g_t1H[B*2048], g_t1L[B*2048];
__device__ float g_akey[B*112];
__device__ unsigned g_bar1, g_bar2;

#define CP_COMMIT asm volatile("cp.async.commit_group;" ::: "memory")
#define CP_WAIT0  asm volatile("cp.async.wait_group 0;" ::: "memory")
#define CP_WAIT1  asm volatile("cp.async.wait_group 1;" ::: "memory")

__device__ __forceinline__ void ldmx4(uint32_t a, uint32_t* r) {
    asm volatile("ldmatrix.sync.aligned.m8n8.x4.shared.b16 {%0,%1,%2,%3}, [%4];"
                 : "=r"(r[0]),"=r"(r[1]),"=r"(r[2]),"=r"(r[3]) : "r"(a));
}
__device__ __forceinline__ void ldmx2(uint32_t a, uint32_t* r) {
    asm volatile("ldmatrix.sync.aligned.m8n8.x2.shared.b16 {%0,%1}, [%2];"
                 : "=r"(r[0]),"=r"(r[1]) : "r"(a));
}
__device__ __forceinline__ void mma16816(float* c, const uint32_t* a, const uint32_t* b) {
    asm volatile("mma.sync.aligned.m16n8k16.row.col.f32.bf16.bf16.f32 "
                 "{%0,%1,%2,%3},{%4,%5,%6,%7},{%8,%9},{%0,%1,%2,%3};"
                 : "+f"(c[0]),"+f"(c[1]),"+f"(c[2]),"+f"(c[3])
                 : "r"(a[0]),"r"(a[1]),"r"(a[2]),"r"(a[3]),"r"(b[0]),"r"(b[1]));
}
__device__ __forceinline__ void cpa16(uint32_t d, const void* s) {
    asm volatile("cp.async.cg.shared.global [%0], [%1], 16;" :: "r"(d),"l"(s));
}
__device__ __forceinline__ void grid_sync(unsigned* bar, unsigned target) {
    __syncthreads();
    if (threadIdx.x == 0) {
        __threadfence();
        atomicAdd(bar, 1u);
        volatile unsigned* vb = (volatile unsigned*)bar;
        while (*vb < target) __nanosleep(64);
        __threadfence();
    }
    __syncthreads();
}

// ---------------- setup kernels ----------------
__global__ void convw_kernel(__nv_bfloat16* dh, __nv_bfloat16* dl,
                             const float* __restrict__ s1, const float* __restrict__ s2,
                             int Npad, int Nreal, int Kpad, int Kreal, int lds, int mode) {
    int64_t tot = (int64_t)Npad * Kpad;
    int64_t stride = (int64_t)gridDim.x * blockDim.x;
    for (int64_t i = (int64_t)blockIdx.x*blockDim.x + threadIdx.x; i < tot; i += stride) {
        int n = (int)(i / Kpad), k = (int)(i % Kpad);
        float v = 0.f;
        if (mode == 0) { if (n < Nreal && k < Kreal) v = s1[(int64_t)n*lds + k]; }
        else {
            int orig = (n & 3)*1024 + (n >> 2);
            if (mode == 1) { if (k < Kreal) v = s1[(int64_t)orig*lds + k]; }
            else {
                if (k < 1024) v = s1[(int64_t)orig*1024 + k];
                else if (k < 1324) v = s2[(int64_t)orig*856 + 556 + (k-1024)];
            }
        }
        __nv_bfloat16 hv = __float2bfloat16(v);
        dh[i] = hv;
        dl[i] = __float2bfloat16(v - __bfloat162float(hv));
    }
}

__global__ void gather_kernel(const int* __restrict__ src_seqs, const int* __restrict__ trg_nt,
                              const int* __restrict__ par_nt, const int* __restrict__ par_lex,
                              const float* __restrict__ lex_emb, const float* __restrict__ nt_emb) {
    if (blockIdx.x == 0 && threadIdx.x == 0) { g_bar1 = 0u; g_bar2 = 0u; }
    const int64_t nse = (int64_t)S_SRC*B*KSE;
    const int64_t nae = (int64_t)S_TRG*B*KAE;
    int64_t stride = (int64_t)gridDim.x * blockDim.x;
    for (int64_t i = (int64_t)blockIdx.x*blockDim.x + threadIdx.x; i < nse; i += stride) {
        {
            int d = (int)(i % KSE), r = (int)(i / KSE);
            int s = r >> 7, b = r & 127;
            float v = (d < 300) ? lex_emb[(int64_t)src_seqs[b*S_SRC+s]*300 + d] : 0.f;
            __nv_bfloat16 hv = __float2bfloat16(v);
            g_seH[i] = hv; g_seL[i] = __float2bfloat16(v - __bfloat162float(hv));
        }
        if (i < nae) {
            int d = (int)(i % KAE), r = (int)(i / KAE);
            int t = r >> 7, b = r & 127;
            float v = 0.f;
            if (d < 128)      v = nt_emb[(int64_t)trg_nt[b*S_TRG+t]*128 + d];
            else if (d < 256) v = nt_emb[(int64_t)par_nt[b*S_TRG+t]*128 + (d-128)];
            else if (d < 556) v = lex_emb[(int64_t)par_lex[b*S_TRG+t]*300 + (d-256)];
            __nv_bfloat16 hv = __float2bfloat16(v);
            g_aeH[i] = hv; g_aeL[i] = __float2bfloat16(v - __bfloat162float(hv));
        }
        if (i < 2*B*KDR) { g_dAH[i] = __float2bfloat16(0.f); g_dAL[i] = __float2bfloat16(0.f); }
        if (i < 2*B*H)   { g_ehH[i] = __float2bfloat16(0.f); g_ehL[i] = __float2bfloat16(0.f); }
        if (i < B*H)     g_ec[i] = 0.f;
    }
}

// ============ persistent recurrence machinery ============
// stream stage rows(72 bf16): 0..127 A_hi, 128..255 A_lo, 256..287 W_lo
__device__ __forceinline__ void stream_chunk(uint32_t st, int t, int k0,
    const __nv_bfloat16* __restrict__ Ah, const __nv_bfloat16* __restrict__ Al, int ldA,
    const __nv_bfloat16* __restrict__ Wl, int ldW, int nbase)
{
#pragma unroll
    for (int i = 0; i < 9; i++) {
        int u = i*256 + t;
        int row = u >> 3, grp = u & 7;
        const __nv_bfloat16* src;
        if (row < 128)      src = Ah + (int64_t)row*ldA + k0 + grp*8;
        else if (row < 256) src = Al + (int64_t)(row-128)*ldA + k0 + grp*8;
        else                src = Wl + (int64_t)(nbase + row - 256)*ldW + k0 + grp*8;
        cpa16(st + (uint32_t)(row*72 + grp*8)*2u, src);
    }
    CP_COMMIT;
}

template<int KCH>
__device__ __forceinline__ void load_resident(uint32_t smW, int t,
    const __nv_bfloat16* __restrict__ Whg, int ldW, int nbase)
{
    int rr = (t >> 3) & 31, grp = t & 7;
#pragma unroll
    for (int i = 0; i < KCH; i++)
        cpa16(smW + (uint32_t)((i*32 + rr)*72 + grp*8)*2u,
              Whg + (int64_t)(nbase + rr)*ldW + i*64 + grp*8);
    CP_COMMIT; CP_WAIT0;
    __syncthreads();
}

__device__ __forceinline__ void mma_chunk(uint32_t smWc, uint32_t st,
    int lane, int wm, int wn, float acc[2][2][4])
{
#pragma unroll
    for (int kk16 = 0; kk16 < 64; kk16 += 16) {
        uint32_t bh[2][2], bl[2][2];
#pragma unroll
        for (int nf = 0; nf < 2; nf++) {
            int rowW = wn*16 + nf*8 + (lane & 7);
            int kcol = kk16 + ((lane >> 3) & 1)*8;
            ldmx2(smWc + (uint32_t)(rowW*72 + kcol)*2u, bh[nf]);
            ldmx2(st + (uint32_t)((256 + rowW)*72 + kcol)*2u, bl[nf]);
        }
#pragma unroll
        for (int mf = 0; mf < 2; mf++) {
            int rowA = wm*32 + mf*16 + (lane & 7) + ((lane >> 3) & 1)*8;
            int kcol = kk16 + ((lane >> 4) & 1)*8;
            uint32_t ah[4], al[4];
            ldmx4(st + (uint32_t)(rowA*72 + kcol)*2u, ah);
            ldmx4(st + (uint32_t)((128 + rowA)*72 + kcol)*2u, al);
#pragma unroll
            for (int nf = 0; nf < 2; nf++) {
                mma16816(acc[mf][nf], ah, bh[nf]);
                mma16816(acc[mf][nf], al, bh[nf]);
                mma16816(acc[mf][nf], ah, bl[nf]);
            }
        }
    }
}

template<int KCH>
__device__ __forceinline__ void gemm_phase(uint32_t smW, uint32_t smS, int t, int lane,
    int wm, int wn,
    const __nv_bfloat16* __restrict__ Ah, const __nv_bfloat16* __restrict__ Al, int ldA,
    const __nv_bfloat16* __restrict__ Wlg, int ldW, int nbase, float acc[2][2][4])
{
    stream_chunk(smS, t, 0, Ah, Al, ldA, Wlg, ldW, nbase);
    stream_chunk(smS + STGB, t, 64, Ah, Al, ldA, Wlg, ldW, nbase);
    for (int c = 0; c < KCH; c++) {
        if (c < KCH - 1) { CP_WAIT1; } else { CP_WAIT0; }
        __syncthreads();
        if (c + 2 < KCH)
            stream_chunk(smS + ((c+2)%3)*STGB, t, (c+2)*64, Ah, Al, ldA, Wlg, ldW, nbase);
        mma_chunk(smW + (uint32_t)c*(32*72*2), smS + (c%3)*STGB, lane, wm, wn, acc);
    }
    __syncthreads();
}

// ---------------- persistent encoder ----------------
__global__ __launch_bounds__(256) void enc_persist(const float* __restrict__ biasv,
                                                   const int* __restrict__ lens) {
    extern __shared__ char smraw[];
    const uint32_t smb = (uint32_t)__cvta_generic_to_shared(smraw);
    const uint32_t smW = smb;
    const uint32_t smS = smb + (uint32_t)(ECH*32*72*2);
    const int t = threadIdx.x;
    const int lane = t & 31, w = t >> 5;
    const int wm = w & 3, wn = w >> 2;
    const int nbase = blockIdx.x*32;
    const int g2 = lane >> 2, q2 = (lane & 3)*2;

    load_resident<ECH>(smW, t, g_WerH, KE, nbase);

    unsigned target = 0;
    for (int s = 0; s < S_SRC; s++) {
        const int p = s & 1;
        const __nv_bfloat16* Ah = g_ehH + p*B*H;
        const __nv_bfloat16* Al = g_ehL + p*B*H;
        __nv_bfloat16* HoH = g_ehH + (p^1)*B*H;
        __nv_bfloat16* HoL = g_ehL + (p^1)*B*H;
        const float* add = g_encpre + (int64_t)s*B*4096;

        float acc[2][2][4];
#pragma unroll
        for (int a = 0; a < 2; a++)
#pragma unroll
            for (int b2 = 0; b2 < 2; b2++)
#pragma unroll
                for (int r = 0; r < 4; r++) acc[a][b2][r] = 0.f;

        gemm_phase<ECH>(smW, smS, t, lane, wm, wn, Ah, Al, H, g_WerL, KE, nbase, acc);

        float* zb = (float*)(smraw + ECH*32*72*2);
#pragma unroll
        for (int mf = 0; mf < 2; mf++)
#pragma unroll
            for (int nf = 0; nf < 2; nf++)
#pragma unroll
                for (int r = 0; r < 4; r++) {
                    int row = wm*32 + mf*16 + g2 + (r >> 1)*8;
                    int col = wn*16 + nf*8 + q2 + (r & 1);
                    zb[row*33 + col] = acc[mf][nf][r];
                }
        __syncthreads();

        const int b = t & 127;
        const int jj0 = (t >> 7)*4;
        bool valid = s < lens[b];
        __nv_bfloat16 z16 = __float2bfloat16(0.f);
#pragma unroll
        for (int jj = jj0; jj < jj0 + 4; jj++) {
            int jglob = (nbase >> 2) + jj;
            float4 pre = *(const float4*)&add[(int64_t)b*4096 + nbase + jj*4];
            float zi = zb[b*33 + jj*4 + 0] + pre.x + biasv[jglob];
            float zf = zb[b*33 + jj*4 + 1] + pre.y + biasv[1024 + jglob];
            float zg = zb[b*33 + jj*4 + 2] + pre.z + biasv[2048 + jglob];
            float zo = zb[b*33 + jj*4 + 3] + pre.w + biasv[3072 + jglob];
            float cold = g_ec[b*H + jglob];
            float si = 1.f/(1.f + expf(-zi));
            float sf = 1.f/(1.f + expf(-zf));
            float so = 1.f/(1.f + expf(-zo));
            float c2 = sf*cold + si*tanhf(zg);
            float h2 = so*tanhf(c2);
            if (valid) g_ec[b*H + jglob] = c2;
            __nv_bfloat16 nh = __float2bfloat16(h2);
            __nv_bfloat16 nl = __float2bfloat16(h2 - __bfloat162float(nh));
            HoH[b*H + jglob] = valid ? nh : Ah[b*H + jglob];
            HoL[b*H + jglob] = valid ? nl : Al[b*H + jglob];
            g_shH[((int64_t)b*S_SRC + s)*H + jglob] = valid ? nh : z16;
            g_shL[((int64_t)b*S_SRC + s)*H + jglob] = valid ? nl : z16;
        }
        grid_sync(&g_bar1, target += 128);
    }
}

// ---------------- persistent decoder ----------------
// mini stage rows: 0..127 A_hi, 128..255 A_lo, 256..263 Wa_hi, 264..271 Wa_lo
__device__ __forceinline__ void stream_mini(uint32_t st, int t, int k0,
    const __nv_bfloat16* __restrict__ Ah, const __nv_bfloat16* __restrict__ Al, int nb8)
{
#pragma unroll
    for (int i = 0; i < 9; i++) {
        int u = i*256 + t;
        if (u >= 2176) break;
        int row = u >> 3, grp = u & 7;
        const __nv_bfloat16* src;
        if (row < 128)      src = Ah + (int64_t)row*KDR + k0 + grp*8;
        else if (row < 256) src = Al + (int64_t)(row-128)*KDR + k0 + grp*8;
        else if (row < 264) src = g_WaH + (int64_t)(nb8 + row - 256)*1024 + k0 + grp*8;
        else                src = g_WaL + (int64_t)(nb8 + row - 264)*1024 + k0 + grp*8;
        cpa16(st + (uint32_t)(row*72 + grp*8)*2u, src);
    }
    CP_COMMIT;
}

__global__ __launch_bounds__(256) void dec_persist(const float* __restrict__ biasv,
                                                   const float* __restrict__ ba_,
                                                   const int* __restrict__ lens,
                                                   float* __restrict__ outF) {
    extern __shared__ char smraw[];
    __shared__ float s_ak[112];
    __shared__ float s_en[128];
    __shared__ float s_red[8];
    const uint32_t smb = (uint32_t)__cvta_generic_to_shared(smraw);
    const uint32_t smW = smb;
    const uint32_t smS = smb + (uint32_t)(DCH*32*72*2);
    const int t = threadIdx.x;
    const int lane = t & 31, w = t >> 5;
    const int wm = w & 3, wn = w >> 2;
    const int nbase = blockIdx.x*32;
    const int g2 = lane >> 2, q2 = (lane & 3)*2;
    const int myb = blockIdx.x;

    load_resident<DCH>(smW, t, g_WdrH, KDR, nbase);

    unsigned target = 0;
    for (int ts = 0; ts < S_TRG; ts++) {
        const int p = ts & 1;
        __nv_bfloat16* dAh = g_dAH + p*B*KDR;
        __nv_bfloat16* dAl = g_dAL + p*B*KDR;
        __nv_bfloat16* nAh = g_dAH + (p^1)*B*KDR;
        __nv_bfloat16* nAl = g_dAL + (p^1)*B*KDR;

        // phase A1: a_key mini-GEMM on blocks 0..13 (N=8 each)
        if (blockIdx.x < 14) {
            const int nb8 = blockIdx.x*8;
            float acm[4] = {0.f,0.f,0.f,0.f};
            stream_mini(smS, t, 0, dAh, dAl, nb8);
            for (int c = 0; c < 16; c++) {
                if (c < 15) stream_mini(smS + ((c+1)&1)*STGB, t, (c+1)*64, dAh, dAl, nb8);
                if (c < 15) { CP_WAIT1; } else { CP_WAIT0; }
                __syncthreads();
                uint32_t st = smS + (c & 1)*STGB;
#pragma unroll
                for (int kk16 = 0; kk16 < 64; kk16 += 16) {
                    uint32_t bh[2], bl[2];
                    int rowW = lane & 7;
                    int kcolW = kk16 + ((lane >> 3) & 1)*8;
                    ldmx2(st + (uint32_t)((256 + rowW)*72 + kcolW)*2u, bh);
                    ldmx2(st + (uint32_t)((264 + rowW)*72 + kcolW)*2u, bl);
                    int rowA = w*16 + (lane & 7) + ((lane >> 3) & 1)*8;
                    int kcolA = kk16 + ((lane >> 4) & 1)*8;
                    uint32_t ah[4], al[4];
                    ldmx4(st + (uint32_t)(rowA*72 + kcolA)*2u, ah);
                    ldmx4(st + (uint32_t)((128 + rowA)*72 + kcolA)*2u, al);
                    mma16816(acm, ah, bh);
                    mma16816(acm, al, bh);
                    mma16816(acm, ah, bl);
                }
                __syncthreads();
            }
#pragma unroll
            for (int r = 0; r < 4; r++) {
                int row = w*16 + g2 + (r >> 1)*8;
                int gc = nb8 + q2 + (r & 1);
                float bb = (gc < 100) ? ba_[gc] : 0.f;
                g_akey[row*112 + gc] = tanhf(acm[r] + bb);
            }
        }
        grid_sync(&g_bar2, target += 128);

        // phase A2: softmax + context for batch myb
        {
            if (t < 112) s_ak[t] = g_akey[myb*112 + t];
            __syncthreads();
            float ex = 0.f;
            if (t < 128) {
                int L = lens[myb];
                const float* qk = g_qkey + ((int64_t)myb*S_SRC + t)*112;
                float pp = 0.f;
#pragma unroll 4
                for (int d = 0; d < 100; d++) pp = fmaf(qk[d], s_ak[d], pp);
                float e = (t < L) ? pp : -1e9f;
                float mx = e;
                for (int o = 16; o; o >>= 1) mx = fmaxf(mx, __shfl_xor_sync(0xffffffffu, mx, o));
                if (lane == 0) s_red[w] = mx;
                s_en[t] = e;
            }
            __syncthreads();
            if (t < 128) {
                float mx = fmaxf(fmaxf(s_red[0], s_red[1]), fmaxf(s_red[2], s_red[3]));
                ex = expf(s_en[t] - mx);
                float sm = ex;
                for (int o = 16; o; o >>= 1) sm += __shfl_xor_sync(0xffffffffu, sm, o);
                if (lane == 0) s_red[4 + w] = sm;
            }
            __syncthreads();
            if (t < 128) s_en[t] = ex;
            __syncthreads();
            float denom = s_red[4] + s_red[5] + s_red[6] + s_red[7];
            for (int d = t; d < 300; d += 256) {
                float c = 0.f;
#pragma unroll 4
                for (int s2 = 0; s2 < S_SRC; s2++)
                    c = fmaf(s_en[s2], g_qval[((int64_t)myb*S_SRC + s2)*304 + d], c);
                c /= denom;
                __nv_bfloat16 hv = __float2bfloat16(c);
                dAh[(int64_t)myb*KDR + 1024 + d] = hv;
                dAl[(int64_t)myb*KDR + 1024 + d] = __float2bfloat16(c - __bfloat162float(hv));
            }
        }
        grid_sync(&g_bar2, target += 128);

        // phase B: recurrent GEMM + LSTM epilogue
        {
            const float* add = g_decpre + (int64_t)ts*B*4096;
            float acc[2][2][4];
#pragma unroll
            for (int a = 0; a < 2; a++)
#pragma unroll
                for (int b2 = 0; b2 < 2; b2++)
#pragma unroll
                    for (int r = 0; r < 4; r++) acc[a][b2][r] = 0.f;

            gemm_phase<DCH>(smW, smS, t, lane, wm, wn, dAh, dAl, KDR, g_WdrL, KDR, nbase, acc);

            float* zb = (float*)(smraw + DCH*32*72*2);
#pragma unroll
            for (int mf = 0; mf < 2; mf++)
#pragma unroll
                for (int nf = 0; nf < 2; nf++)
#pragma unroll
                    for (int r = 0; r < 4; r++) {
                        int row = wm*32 + mf*16 + g2 + (r >> 1)*8;
                        int col = wn*16 + nf*8 + q2 + (r & 1);
                        zb[row*33 + col] = acc[mf][nf][r];
                    }
            __syncthreads();

            const int b = t & 127;
            const int jj0 = (t >> 7)*4;
#pragma unroll
            for (int jj = jj0; jj < jj0 + 4; jj++) {
                int jglob = (nbase >> 2) + jj;
                float4 pre = *(const float4*)&add[(int64_t)b*4096 + nbase + jj*4];
                float zi = zb[b*33 + jj*4 + 0] + pre.x + biasv[jglob];
                float zf = zb[b*33 + jj*4 + 1] + pre.y + biasv[1024 + jglob];
                float zg = zb[b*33 + jj*4 + 2] + pre.z + biasv[2048 + jglob];
                float zo = zb[b*33 + jj*4 + 3] + pre.w + biasv[3072 + jglob];
                float cold = g_dc[b*H + jglob];
                float si = 1.f/(1.f + expf(-zi));
                float sf = 1.f/(1.f + expf(-zf));
                float so = 1.f/(1.f + expf(-zo));
                float c2 = sf*cold + si*tanhf(zg);
                float h2 = so*tanhf(c2);
                g_dc[b*H + jglob] = c2;
                __nv_bfloat16 nh = __float2bfloat16(h2);
                __nv_bfloat16 nl = __float2bfloat16(h2 - __bfloat162float(nh));
                nAh[(int64_t)b*KDR + jglob] = nh;
                nAl[(int64_t)b*KDR + jglob] = nl;
                outF[((int64_t)b*S_TRG + ts)*H + jglob] = h2;
            }
        }
        grid_sync(&g_bar2, target += 128);
    }
}

// ---------------- one-shot GEMM (setup / batched ops) ----------------
__device__ __forceinline__ void load_chunk_g(uint32_t smb, int buf, int t, int k0,
    const __nv_bfloat16* __restrict__ Ah, const __nv_bfloat16* __restrict__ Al, int ldA, int mbase,
    const __nv_bfloat16* __restrict__ Wh, const __nv_bfloat16* __restrict__ Wl, int ldW, int nbase)
{
#pragma unroll
    for (int i = 0; i < 8; i++) {
        int u = i*256 + t;
        int hl = u >> 10, rem = u & 1023;
        int row = rem >> 3, grp = rem & 7;
        const __nv_bfloat16* src = (hl ? Al : Ah) + (int64_t)(mbase + row)*ldA + k0 + grp*8;
        cpa16(smb + (uint32_t)(((buf*2 + hl)*128 + row)*72 + grp*8)*2u, src);
    }
#pragma unroll
    for (int i = 0; i < 2; i++) {
        int u = i*256 + t;
        int hl = u >> 8, rem = u & 255;
        int row = rem >> 3, grp = rem & 7;
        const __nv_bfloat16* src = (hl ? Wl : Wh) + (int64_t)(nbase + row)*ldW + k0 + grp*8;
        cpa16(smb + (uint32_t)(36864 + ((buf*2 + hl)*32 + row)*72 + grp*8)*2u, src);
    }
    CP_COMMIT;
}

template<int OUT, int ACT>   // OUT: 0 fp32, 1 bf16 hi/lo ; ACT: 0 none, 1 relu, 2 tanh
__global__ __launch_bounds__(256) void mma_gemm(
    const __nv_bfloat16* __restrict__ Ah, const __nv_bfloat16* __restrict__ Al, int ldA,
    const __nv_bfloat16* __restrict__ Wh, const __nv_bfloat16* __restrict__ Wl, int ldW,
    int N, int KT, const float* __restrict__ bias,
    float* __restrict__ Cf, __nv_bfloat16* __restrict__ Ch, __nv_bfloat16* __restrict__ Cl, int ldC)
{
    extern __shared__ char smraw[];
    uint32_t smb = (uint32_t)__cvta_generic_to_shared(smraw);
    const int t = threadIdx.x;
    const int lane = t & 31, w = t >> 5;
    const int wm = w & 3, wn = w >> 2;
    const int mbase = blockIdx.y*128;
    const int nbase = blockIdx.x*32;

    float acc[2][2][4];
#pragma unroll
    for (int a = 0; a < 2; a++)
#pragma unroll
        for (int b2 = 0; b2 < 2; b2++)
#pragma unroll
            for (int r = 0; r < 4; r++) acc[a][b2][r] = 0.f;

    load_chunk_g(smb, 0, t, 0, Ah, Al, ldA, mbase, Wh, Wl, ldW, nbase);

    for (int kc = 0; kc < KT; kc++) {
        const int cur = kc & 1;
        if (kc + 1 < KT) {
            load_chunk_g(smb, cur ^ 1, t, (kc+1)*64, Ah, Al, ldA, mbase, Wh, Wl, ldW, nbase);
            CP_WAIT1;
        } else { CP_WAIT0; }
        __syncthreads();
#pragma unroll
        for (int kk16 = 0; kk16 < 64; kk16 += 16) {
            uint32_t bh[2][2], bl[2][2];
#pragma unroll
            for (int nf = 0; nf < 2; nf++) {
                int rowW = wn*16 + nf*8 + (lane & 7);
                int kcol = kk16 + ((lane >> 3) & 1)*8;
                ldmx2(smb + (uint32_t)(36864 + ((cur*2+0)*32 + rowW)*72 + kcol)*2u, bh[nf]);
                ldmx2(smb + (uint32_t)(36864 + ((cur*2+1)*32 + rowW)*72 + kcol)*2u, bl[nf]);
            }
#pragma unroll
            for (int mf = 0; mf < 2; mf++) {
                int rowA = wm*32 + mf*16 + (lane & 7) + ((lane >> 3) & 1)*8;
                int kcol = kk16 + ((lane >> 4) & 1)*8;
                uint32_t ah[4], al[4];
                ldmx4(smb + (uint32_t)(((cur*2+0)*128 + rowA)*72 + kcol)*2u, ah);
                ldmx4(smb + (uint32_t)(((cur*2+1)*128 + rowA)*72 + kcol)*2u, al);
#pragma unroll
                for (int nf = 0; nf < 2; nf++) {
                    mma16816(acc[mf][nf], ah, bh[nf]);
                    mma16816(acc[mf][nf], al, bh[nf]);
                    mma16816(acc[mf][nf], ah, bl[nf]);
                }
            }
        }
        __syncthreads();
    }

    const int g2 = lane >> 2, q2 = (lane & 3)*2;
#pragma unroll
    for (int mf = 0; mf < 2; mf++)
#pragma unroll
        for (int nf = 0; nf < 2; nf++)
#pragma unroll
            for (int r = 0; r < 4; r++) {
                int row = mbase + wm*32 + mf*16 + g2 + (r >> 1)*8;
                int col = nbase + wn*16 + nf*8 + q2 + (r & 1);
                if (col < N) {
                    float v = acc[mf][nf][r];
                    if (bias) v += bias[col];
                    if (ACT == 1) v = fmaxf(v, 0.f);
                    if (ACT == 2) v = tanhf(v);
                    if (OUT == 0) Cf[(int64_t)row*ldC + col] = v;
                    else {
                        __nv_bfloat16 hv = __float2bfloat16(v);
                        Ch[(int64_t)row*ldC + col] = hv;
                        Cl[(int64_t)row*ldC + col] = __float2bfloat16(v - __bfloat162float(hv));
                    }
                }
            }
}

// ---------------- launcher ----------------
#define GSA(p, s) cudaGetSymbolAddress((void**)&p, s)

extern "C" void kernel_launch(void* const* d_in, const int* in_sizes, int n_in,
                              void* d_out, int out_size) {
    const int*   src_seqs = (const int*)d_in[0];
    const int*   src_len  = (const int*)d_in[1];
    const int*   trg_nt   = (const int*)d_in[2];
    const int*   par_nt   = (const int*)d_in[3];
    const int*   par_lex  = (const int*)d_in[4];
    const float* lex_emb  = (const float*)d_in[5];
    const float* nt_emb   = (const float*)d_in[6];
    const float* enc_Wih  = (const float*)d_in[7];
    const float* enc_Whh  = (const float*)d_in[8];
    const float* enc_b    = (const float*)d_in[9];
    const float* dec_Wih  = (const float*)d_in[10];
    const float* dec_Whh  = (const float*)d_in[11];
    const float* dec_b    = (const float*)d_in[12];
    const float* Wh1 = (const float*)d_in[13];
    const float* bh1 = (const float*)d_in[14];
    const float* Wh2 = (const float*)d_in[15];
    const float* bh2 = (const float*)d_in[16];
    const float* Wc1 = (const float*)d_in[17];
    const float* bc1 = (const float*)d_in[18];
    const float* Wc2 = (const float*)d_in[19];
    const float* bc2 = (const float*)d_in[20];
    const float* Wa  = (const float*)d_in[21];
    const float* ba  = (const float*)d_in[22];
    const float* Wqk = (const float*)d_in[23];
    const float* bqk = (const float*)d_in[24];
    const float* Wqv = (const float*)d_in[25];
    const float* bqv = (const float*)d_in[26];
    float* out = (float*)d_out;

    cudaFuncSetAttribute(mma_gemm<0,0>, cudaFuncAttributeMaxDynamicSharedMemorySize, GEN_SMEM);
    cudaFuncSetAttribute(mma_gemm<0,2>, cudaFuncAttributeMaxDynamicSharedMemorySize, GEN_SMEM);
    cudaFuncSetAttribute(mma_gemm<1,0>, cudaFuncAttributeMaxDynamicSharedMemorySize, GEN_SMEM);
    cudaFuncSetAttribute(mma_gemm<1,1>, cudaFuncAttributeMaxDynamicSharedMemorySize, GEN_SMEM);
    cudaFuncSetAttribute(enc_persist, cudaFuncAttributeMaxDynamicSharedMemorySize, ENC_SMEM);
    cudaFuncSetAttribute(dec_persist, cudaFuncAttributeMaxDynamicSharedMemorySize, DEC_SMEM);

    __nv_bfloat16 *WerH,*WerL,*WdrH,*WdrL,*WeiH,*WeiL,*WdiH,*WdiL;
    __nv_bfloat16 *WqkH,*WqkL,*WqvH,*WqvL,*WaH,*WaL;
    __nv_bfloat16 *Wh1H,*Wh1L,*Wh2H,*Wh2L,*Wc1H,*Wc1L,*Wc2H,*Wc2L;
    __nv_bfloat16 *seH,*seL,*aeH,*aeL,*shH,*shL,*ehH,*ehL,*dAH,*dAL,*ecH,*ecL,*t1H,*t1L;
    float *encpre,*decpre,*qkey,*qval,*ec,*dc;
    GSA(WerH,g_WerH); GSA(WerL,g_WerL); GSA(WdrH,g_WdrH); GSA(WdrL,g_WdrL);
    GSA(WeiH,g_WeiH); GSA(WeiL,g_WeiL); GSA(WdiH,g_WdiH); GSA(WdiL,g_WdiL);
    GSA(WqkH,g_WqkH); GSA(WqkL,g_WqkL); GSA(WqvH,g_WqvH); GSA(WqvL,g_WqvL);
    GSA(WaH,g_WaH);   GSA(WaL,g_WaL);
    GSA(Wh1H,g_Wh1H); GSA(Wh1L,g_Wh1L); GSA(Wh2H,g_Wh2H); GSA(Wh2L,g_Wh2L);
    GSA(Wc1H,g_Wc1H); GSA(Wc1L,g_Wc1L); GSA(Wc2H,g_Wc2H); GSA(Wc2L,g_Wc2L);
    GSA(seH,g_seH); GSA(seL,g_seL); GSA(aeH,g_aeH); GSA(aeL,g_aeL);
    GSA(shH,g_shH); GSA(shL,g_shL); GSA(ehH,g_ehH); GSA(ehL,g_ehL);
    GSA(dAH,g_dAH); GSA(dAL,g_dAL); GSA(ecH,g_ecH); GSA(ecL,g_ecL);
    GSA(t1H,g_t1H); GSA(t1L,g_t1L);
    GSA(encpre,g_encpre); GSA(decpre,g_decpre);
    GSA(qkey,g_qkey); GSA(qval,g_qval); GSA(ec,g_ec); GSA(dc,g_dc);

    // setup
    convw_kernel<<<1024, 256>>>(WerH, WerL, enc_Whh, nullptr, 4096, 0, KE, 1024, 1024, 1);
    convw_kernel<<<1024, 256>>>(WdrH, WdrL, dec_Whh, dec_Wih, 4096, 0, KDR, 1324, 0, 2);
    convw_kernel<<<1024, 256>>>(WeiH, WeiL, enc_Wih, nullptr, 4096, 0, KSE, 300, 300, 1);
    convw_kernel<<<1024, 256>>>(WdiH, WdiL, dec_Wih, nullptr, 4096, 0, KAE, 556, 856, 1);
    convw_kernel<<<256, 256>>>(WqkH, WqkL, Wqk, nullptr, 128, 100, 1024, 1024, 1024, 0);
    convw_kernel<<<256, 256>>>(WqvH, WqvL, Wqv, nullptr, 320, 300, 1024, 1024, 1024, 0);
    convw_kernel<<<256, 256>>>(WaH,  WaL,  Wa,  nullptr, 128, 100, 1024, 1024, 1024, 0);
    convw_kernel<<<1024, 256>>>(Wh1H, Wh1L, Wh1, nullptr, 2048, 2048, 1024, 1024, 1024, 0);
    convw_kernel<<<1024, 256>>>(Wh2H, Wh2L, Wh2, nullptr, 1024, 1024, 2048, 2048, 2048, 0);
    convw_kernel<<<1024, 256>>>(Wc1H, Wc1L, Wc1, nullptr, 2048, 2048, 1024, 1024, 1024, 0);
    convw_kernel<<<1024, 256>>>(Wc2H, Wc2L, Wc2, nullptr, 1024, 1024, 2048, 2048, 2048, 0);
    gather_kernel<<<2048, 256>>>(src_seqs, trg_nt, par_nt, par_lex, lex_emb, nt_emb);

    // input-side precompute
    mma_gemm<0,0><<<dim3(128,128), 256, GEN_SMEM>>>(seH, seL, KSE, WeiH, WeiL, KSE,
        4096, KSE/64, nullptr, encpre, nullptr, nullptr, 4096);
    mma_gemm<0,0><<<dim3(128,64), 256, GEN_SMEM>>>(aeH, aeL, KAE, WdiH, WdiL, KAE,
        4096, KAE/64, nullptr, decpre, nullptr, nullptr, 4096);

    // encoder (persistent)
    enc_persist<<<128, 256, ENC_SMEM>>>(enc_b, src_len);
    __nv_bfloat16* ehTH = ehH;   // S_SRC even -> final state in buffer 0
    __nv_bfloat16* ehTL = ehL;

    // attention keys/values
    mma_gemm<0,2><<<dim3(4,128), 256, GEN_SMEM>>>(shH, shL, H, WqkH, WqkL, 1024,
        100, 16, bqk, qkey, nullptr, nullptr, 112);
    mma_gemm<0,0><<<dim3(10,128), 256, GEN_SMEM>>>(shH, shL, H, WqvH, WqvL, 1024,
        300, 16, bqv, qval, nullptr, nullptr, 304);

    // decoder init MLPs
    convw_kernel<<<256, 256>>>(ecH, ecL, ec, nullptr, 128, 128, 1024, 1024, 1024, 0);
    mma_gemm<1,1><<<dim3(64,1), 256, GEN_SMEM>>>(ehTH, ehTL, H, Wh1H, Wh1L, 1024,
        2048, 16, bh1, nullptr, t1H, t1L, 2048);
    mma_gemm<1,0><<<dim3(32,1), 256, GEN_SMEM>>>(t1H, t1L, 2048, Wh2H, Wh2L, 2048,
        1024, 32, bh2, nullptr, dAH, dAL, KDR);
    mma_gemm<1,1><<<dim3(64,1), 256, GEN_SMEM>>>(ecH, ecL, H, Wc1H, Wc1L, 1024,
        2048, 16, bc1, nullptr, t1H, t1L, 2048);
    mma_gemm<0,0><<<dim3(32,1), 256, GEN_SMEM>>>(t1H, t1L, 2048, Wc2H, Wc2L, 2048,
        1024, 32, bc2, dc, nullptr, nullptr, 1024);

    // decoder (persistent, attention fused)
    dec_persist<<<128, 256, DEC_SMEM>>>(dec_b, ba, src_len, out);
}

// round 6
// speedup vs baseline: 1.0296x; 1.0067x over previous
#include <cuda_runtime.h>
#include <cuda_bf16.h>
#include <math.h>
#include <stdint.h>

#define B 128
#define S_SRC 128
#define S_TRG 64
#define H 1024
#define KE 1024
#define KDR 1344
#define KSE 320
#define KAE 576
#define ECH 16
#define DCH 21
#define STGB (288*72*2)
#define ENC_SMEM ((ECH*32*72 + 3*288*72)*2)
#define DEC_SMEM ((DCH*32*72 + 3*288*72)*2)
#define GEN_SMEM 92160

// ---------------- weights (bf16 hi/lo, converted once) ----------------
__device__ __nv_bfloat16 g_WerH[4096*KE],  g_WerL[4096*KE];
__device__ __nv_bfloat16 g_WdrH[4096*KDR], g_WdrL[4096*KDR];
__device__ __nv_bfloat16 g_WeiH[4096*KSE], g_WeiL[4096*KSE];
__device__ __nv_bfloat16 g_WdiH[4096*KAE], g_WdiL[4096*KAE];
__device__ __nv_bfloat16 g_WqkH[128*1024], g_WqkL[128*1024];
__device__ __nv_bfloat16 g_WqvH[320*1024], g_WqvL[320*1024];
__device__ __nv_bfloat16 g_WaH[128*1024],  g_WaL[128*1024];
__device__ __nv_bfloat16 g_Wh1H[2048*1024], g_Wh1L[2048*1024];
__device__ __nv_bfloat16 g_Wh2H[1024*2048], g_Wh2L[1024*2048];
__device__ __nv_bfloat16 g_Wc1H[2048*1024], g_Wc1L[2048*1024];
__device__ __nv_bfloat16 g_Wc2H[1024*2048], g_Wc2L[1024*2048];

// ---------------- activations / state ----------------
__device__ __nv_bfloat16 g_seH[(size_t)S_SRC*B*KSE], g_seL[(size_t)S_SRC*B*KSE];
__device__ __nv_bfloat16 g_aeH[(size_t)S_TRG*B*KAE], g_aeL[(size_t)S_TRG*B*KAE];
__device__ float g_encpre[(size_t)S_SRC*B*4096];
__device__ float g_decpre[(size_t)S_TRG*B*4096];
__device__ __nv_bfloat16 g_shH[(size_t)B*S_SRC*H], g_shL[(size_t)B*S_SRC*H];
__device__ float g_qkey[(size_t)B*S_SRC*112];
__device__ float g_qval[(size_t)B*S_SRC*304];
__device__ __nv_bfloat16 g_ehH[2*B*H], g_ehL[2*B*H];
__device__ __nv_bfloat16 g_dAH[2*B*KDR], g_dAL[2*B*KDR];
__device__ float g_ec[B*H], g_dc[B*H];
__device__ __nv_bfloat16 g_ecH[B*H], g_ecL[B*H];
__device__ __nv_bfloat16 g_t1H[B*2048], g_t1L[B*2048];
__device__ float g_akey[B*112];
__device__ unsigned g_bar1, g_bar2;

#define CP_COMMIT asm volatile("cp.async.commit_group;" ::: "memory")
#define CP_WAIT0  asm volatile("cp.async.wait_group 0;" ::: "memory")
#define CP_WAIT1  asm volatile("cp.async.wait_group 1;" ::: "memory")

__device__ __forceinline__ void ldmx4(uint32_t a, uint32_t* r) {
    asm volatile("ldmatrix.sync.aligned.m8n8.x4.shared.b16 {%0,%1,%2,%3}, [%4];"
                 : "=r"(r[0]),"=r"(r[1]),"=r"(r[2]),"=r"(r[3]) : "r"(a));
}
__device__ __forceinline__ void ldmx2(uint32_t a, uint32_t* r) {
    asm volatile("ldmatrix.sync.aligned.m8n8.x2.shared.b16 {%0,%1}, [%2];"
                 : "=r"(r[0]),"=r"(r[1]) : "r"(a));
}
__device__ __forceinline__ void mma16816(float* c, const uint32_t* a, const uint32_t* b) {
    asm volatile("mma.sync.aligned.m16n8k16.row.col.f32.bf16.bf16.f32 "
                 "{%0,%1,%2,%3},{%4,%5,%6,%7},{%8,%9},{%0,%1,%2,%3};"
                 : "+f"(c[0]),"+f"(c[1]),"+f"(c[2]),"+f"(c[3])
                 : "r"(a[0]),"r"(a[1]),"r"(a[2]),"r"(a[3]),"r"(b[0]),"r"(b[1]));
}
__device__ __forceinline__ void cpa16(uint32_t d, const void* s) {
    asm volatile("cp.async.cg.shared.global [%0], [%1], 16;" :: "r"(d),"l"(s));
}
__device__ __forceinline__ void grid_sync(unsigned* bar, unsigned target) {
    __syncthreads();
    if (threadIdx.x == 0) {
        __threadfence();
        atomicAdd(bar, 1u);
        volatile unsigned* vb = (volatile unsigned*)bar;
        while (*vb < target) __nanosleep(64);
        __threadfence();
    }
    __syncthreads();
}

// ---------------- setup kernels ----------------
__global__ void convw_kernel(__nv_bfloat16* dh, __nv_bfloat16* dl,
                             const float* __restrict__ s1, const float* __restrict__ s2,
                             int Npad, int Nreal, int Kpad, int Kreal, int lds, int mode) {
    int64_t tot = (int64_t)Npad * Kpad;
    int64_t stride = (int64_t)gridDim.x * blockDim.x;
    for (int64_t i = (int64_t)blockIdx.x*blockDim.x + threadIdx.x; i < tot; i += stride) {
        int n = (int)(i / Kpad), k = (int)(i % Kpad);
        float v = 0.f;
        if (mode == 0) { if (n < Nreal && k < Kreal) v = s1[(int64_t)n*lds + k]; }
        else {
            int orig = (n & 3)*1024 + (n >> 2);
            if (mode == 1) { if (k < Kreal) v = s1[(int64_t)orig*lds + k]; }
            else {
                if (k < 1024) v = s1[(int64_t)orig*1024 + k];
                else if (k < 1324) v = s2[(int64_t)orig*856 + 556 + (k-1024)];
            }
        }
        __nv_bfloat16 hv = __float2bfloat16(v);
        dh[i] = hv;
        dl[i] = __float2bfloat16(v - __bfloat162float(hv));
    }
}

__global__ void gather_kernel(const int* __restrict__ src_seqs, const int* __restrict__ trg_nt,
                              const int* __restrict__ par_nt, const int* __restrict__ par_lex,
                              const float* __restrict__ lex_emb, const float* __restrict__ nt_emb) {
    if (blockIdx.x == 0 && threadIdx.x == 0) { g_bar1 = 0u; g_bar2 = 0u; }
    const int64_t nse = (int64_t)S_SRC*B*KSE;
    const int64_t nae = (int64_t)S_TRG*B*KAE;
    int64_t stride = (int64_t)gridDim.x * blockDim.x;
    for (int64_t i = (int64_t)blockIdx.x*blockDim.x + threadIdx.x; i < nse; i += stride) {
        {
            int d = (int)(i % KSE), r = (int)(i / KSE);
            int s = r >> 7, b = r & 127;
            float v = (d < 300) ? lex_emb[(int64_t)src_seqs[b*S_SRC+s]*300 + d] : 0.f;
            __nv_bfloat16 hv = __float2bfloat16(v);
            g_seH[i] = hv; g_seL[i] = __float2bfloat16(v - __bfloat162float(hv));
        }
        if (i < nae) {
            int d = (int)(i % KAE), r = (int)(i / KAE);
            int t = r >> 7, b = r & 127;
            float v = 0.f;
            if (d < 128)      v = nt_emb[(int64_t)trg_nt[b*S_TRG+t]*128 + d];
            else if (d < 256) v = nt_emb[(int64_t)par_nt[b*S_TRG+t]*128 + (d-128)];
            else if (d < 556) v = lex_emb[(int64_t)par_lex[b*S_TRG+t]*300 + (d-256)];
            __nv_bfloat16 hv = __float2bfloat16(v);
            g_aeH[i] = hv; g_aeL[i] = __float2bfloat16(v - __bfloat162float(hv));
        }
        if (i < 2*B*KDR) { g_dAH[i] = __float2bfloat16(0.f); g_dAL[i] = __float2bfloat16(0.f); }
        if (i < 2*B*H)   { g_ehH[i] = __float2bfloat16(0.f); g_ehL[i] = __float2bfloat16(0.f); }
        if (i < B*H)     g_ec[i] = 0.f;
    }
}

// ============ persistent recurrence machinery ============
// stream stage rows(72 bf16): 0..127 A_hi, 128..255 A_lo, 256..287 W_lo
__device__ __forceinline__ void stream_chunk(uint32_t st, int t, int k0,
    const __nv_bfloat16* __restrict__ Ah, const __nv_bfloat16* __restrict__ Al, int ldA,
    const __nv_bfloat16* __restrict__ Wl, int ldW, int nbase)
{
#pragma unroll
    for (int i = 0; i < 9; i++) {
        int u = i*256 + t;
        int row = u >> 3, grp = u & 7;
        const __nv_bfloat16* src;
        if (row < 128)      src = Ah + (int64_t)row*ldA + k0 + grp*8;
        else if (row < 256) src = Al + (int64_t)(row-128)*ldA + k0 + grp*8;
        else                src = Wl + (int64_t)(nbase + row - 256)*ldW + k0 + grp*8;
        cpa16(st + (uint32_t)(row*72 + grp*8)*2u, src);
    }
    CP_COMMIT;
}

template<int KCH>
__device__ __forceinline__ void load_resident(uint32_t smW, int t,
    const __nv_bfloat16* __restrict__ Whg, int ldW, int nbase)
{
    int rr = (t >> 3) & 31, grp = t & 7;
#pragma unroll
    for (int i = 0; i < KCH; i++)
        cpa16(smW + (uint32_t)((i*32 + rr)*72 + grp*8)*2u,
              Whg + (int64_t)(nbase + rr)*ldW + i*64 + grp*8);
    CP_COMMIT; CP_WAIT0;
    __syncthreads();
}

__device__ __forceinline__ void mma_chunk(uint32_t smWc, uint32_t st,
    int lane, int wm, int wn, float acc[2][2][4])
{
#pragma unroll
    for (int kk16 = 0; kk16 < 64; kk16 += 16) {
        uint32_t bh[2][2], bl[2][2];
#pragma unroll
        for (int nf = 0; nf < 2; nf++) {
            int rowW = wn*16 + nf*8 + (lane & 7);
            int kcol = kk16 + ((lane >> 3) & 1)*8;
            ldmx2(smWc + (uint32_t)(rowW*72 + kcol)*2u, bh[nf]);
            ldmx2(st + (uint32_t)((256 + rowW)*72 + kcol)*2u, bl[nf]);
        }
#pragma unroll
        for (int mf = 0; mf < 2; mf++) {
            int rowA = wm*32 + mf*16 + (lane & 7) + ((lane >> 3) & 1)*8;
            int kcol = kk16 + ((lane >> 4) & 1)*8;
            uint32_t ah[4], al[4];
            ldmx4(st + (uint32_t)(rowA*72 + kcol)*2u, ah);
            ldmx4(st + (uint32_t)((128 + rowA)*72 + kcol)*2u, al);
#pragma unroll
            for (int nf = 0; nf < 2; nf++) {
                mma16816(acc[mf][nf], ah, bh[nf]);
                mma16816(acc[mf][nf], al, bh[nf]);
                mma16816(acc[mf][nf], ah, bl[nf]);
            }
        }
    }
}

template<int KCH>
__device__ __forceinline__ void gemm_phase(uint32_t smW, uint32_t smS, int t, int lane,
    int wm, int wn,
    const __nv_bfloat16* __restrict__ Ah, const __nv_bfloat16* __restrict__ Al, int ldA,
    const __nv_bfloat16* __restrict__ Wlg, int ldW, int nbase, float acc[2][2][4])
{
    stream_chunk(smS, t, 0, Ah, Al, ldA, Wlg, ldW, nbase);
    stream_chunk(smS + STGB, t, 64, Ah, Al, ldA, Wlg, ldW, nbase);
    for (int c = 0; c < KCH; c++) {
        if (c < KCH - 1) { CP_WAIT1; } else { CP_WAIT0; }
        __syncthreads();
        if (c + 2 < KCH)
            stream_chunk(smS + ((c+2)%3)*STGB, t, (c+2)*64, Ah, Al, ldA, Wlg, ldW, nbase);
        mma_chunk(smW + (uint32_t)c*(32*72*2), smS + (c%3)*STGB, lane, wm, wn, acc);
    }
    __syncthreads();
}

// ---------------- persistent encoder ----------------
__global__ __launch_bounds__(256) void enc_persist(const float* __restrict__ biasv,
                                                   const int* __restrict__ lens) {
    extern __shared__ char smraw[];
    const uint32_t smb = (uint32_t)__cvta_generic_to_shared(smraw);
    const uint32_t smW = smb;
    const uint32_t smS = smb + (uint32_t)(ECH*32*72*2);
    const int t = threadIdx.x;
    const int lane = t & 31, w = t >> 5;
    const int wm = w & 3, wn = w >> 2;
    const int nbase = blockIdx.x*32;
    const int g2 = lane >> 2, q2 = (lane & 3)*2;

    load_resident<ECH>(smW, t, g_WerH, KE, nbase);

    unsigned target = 0;
    for (int s = 0; s < S_SRC; s++) {
        const int p = s & 1;
        const __nv_bfloat16* Ah = g_ehH + p*B*H;
        const __nv_bfloat16* Al = g_ehL + p*B*H;
        __nv_bfloat16* HoH = g_ehH + (p^1)*B*H;
        __nv_bfloat16* HoL = g_ehL + (p^1)*B*H;
        const float* add = g_encpre + (int64_t)s*B*4096;

        float acc[2][2][4];
#pragma unroll
        for (int a = 0; a < 2; a++)
#pragma unroll
            for (int b2 = 0; b2 < 2; b2++)
#pragma unroll
                for (int r = 0; r < 4; r++) acc[a][b2][r] = 0.f;

        gemm_phase<ECH>(smW, smS, t, lane, wm, wn, Ah, Al, H, g_WerL, KE, nbase, acc);

        float* zb = (float*)(smraw + ECH*32*72*2);
#pragma unroll
        for (int mf = 0; mf < 2; mf++)
#pragma unroll
            for (int nf = 0; nf < 2; nf++)
#pragma unroll
                for (int r = 0; r < 4; r++) {
                    int row = wm*32 + mf*16 + g2 + (r >> 1)*8;
                    int col = wn*16 + nf*8 + q2 + (r & 1);
                    zb[row*33 + col] = acc[mf][nf][r];
                }
        __syncthreads();

        const int b = t & 127;
        const int jj0 = (t >> 7)*4;
        bool valid = s < lens[b];
        __nv_bfloat16 z16 = __float2bfloat16(0.f);
#pragma unroll
        for (int jj = jj0; jj < jj0 + 4; jj++) {
            int jglob = (nbase >> 2) + jj;
            float4 pre = *(const float4*)&add[(int64_t)b*4096 + nbase + jj*4];
            float zi = zb[b*33 + jj*4 + 0] + pre.x + biasv[jglob];
            float zf = zb[b*33 + jj*4 + 1] + pre.y + biasv[1024 + jglob];
            float zg = zb[b*33 + jj*4 + 2] + pre.z + biasv[2048 + jglob];
            float zo = zb[b*33 + jj*4 + 3] + pre.w + biasv[3072 + jglob];
            float cold = g_ec[b*H + jglob];
            float si = 1.f/(1.f + expf(-zi));
            float sf = 1.f/(1.f + expf(-zf));
            float so = 1.f/(1.f + expf(-zo));
            float c2 = sf*cold + si*tanhf(zg);
            float h2 = so*tanhf(c2);
            if (valid) g_ec[b*H + jglob] = c2;
            __nv_bfloat16 nh = __float2bfloat16(h2);
            __nv_bfloat16 nl = __float2bfloat16(h2 - __bfloat162float(nh));
            HoH[b*H + jglob] = valid ? nh : Ah[b*H + jglob];
            HoL[b*H + jglob] = valid ? nl : Al[b*H + jglob];
            g_shH[((int64_t)b*S_SRC + s)*H + jglob] = valid ? nh : z16;
            g_shL[((int64_t)b*S_SRC + s)*H + jglob] = valid ? nl : z16;
        }
        grid_sync(&g_bar1, target += 128);
    }
}

// ---------------- persistent decoder ----------------
// mini stage rows: 0..127 A_hi, 128..255 A_lo, 256..263 Wa_hi, 264..271 Wa_lo
__device__ __forceinline__ void stream_mini(uint32_t st, int t, int k0,
    const __nv_bfloat16* __restrict__ Ah, const __nv_bfloat16* __restrict__ Al, int nb8)
{
#pragma unroll
    for (int i = 0; i < 9; i++) {
        int u = i*256 + t;
        if (u >= 2176) break;
        int row = u >> 3, grp = u & 7;
        const __nv_bfloat16* src;
        if (row < 128)      src = Ah + (int64_t)row*KDR + k0 + grp*8;
        else if (row < 256) src = Al + (int64_t)(row-128)*KDR + k0 + grp*8;
        else if (row < 264) src = g_WaH + (int64_t)(nb8 + row - 256)*1024 + k0 + grp*8;
        else                src = g_WaL + (int64_t)(nb8 + row - 264)*1024 + k0 + grp*8;
        cpa16(st + (uint32_t)(row*72 + grp*8)*2u, src);
    }
    CP_COMMIT;
}

__global__ __launch_bounds__(256) void dec_persist(const float* __restrict__ biasv,
                                                   const float* __restrict__ ba_,
                                                   const int* __restrict__ lens,
                                                   float* __restrict__ outF) {
    extern __shared__ char smraw[];
    __shared__ float s_ak[112];
    __shared__ float s_en[128];
    __shared__ float s_red[8];
    const uint32_t smb = (uint32_t)__cvta_generic_to_shared(smraw);
    const uint32_t smW = smb;
    const uint32_t smS = smb + (uint32_t)(DCH*32*72*2);
    const int t = threadIdx.x;
    const int lane = t & 31, w = t >> 5;
    const int wm = w & 3, wn = w >> 2;
    const int nbase = blockIdx.x*32;
    const int g2 = lane >> 2, q2 = (lane & 3)*2;
    const int myb = blockIdx.x;

    load_resident<DCH>(smW, t, g_WdrH, KDR, nbase);

    unsigned target = 0;
    for (int ts = 0; ts < S_TRG; ts++) {
        const int p = ts & 1;
        __nv_bfloat16* dAh = g_dAH + p*B*KDR;
        __nv_bfloat16* dAl = g_dAL + p*B*KDR;
        __nv_bfloat16* nAh = g_dAH + (p^1)*B*KDR;
        __nv_bfloat16* nAl = g_dAL + (p^1)*B*KDR;

        // phase A1: a_key mini-GEMM on blocks 0..13 (N=8 each)
        if (blockIdx.x < 14) {
            const int nb8 = blockIdx.x*8;
            float acm[4] = {0.f,0.f,0.f,0.f};
            stream_mini(smS, t, 0, dAh, dAl, nb8);
            for (int c = 0; c < 16; c++) {
                if (c < 15) stream_mini(smS + ((c+1)&1)*STGB, t, (c+1)*64, dAh, dAl, nb8);
                if (c < 15) { CP_WAIT1; } else { CP_WAIT0; }
                __syncthreads();
                uint32_t st = smS + (c & 1)*STGB;
#pragma unroll
                for (int kk16 = 0; kk16 < 64; kk16 += 16) {
                    uint32_t bh[2], bl[2];
                    int rowW = lane & 7;
                    int kcolW = kk16 + ((lane >> 3) & 1)*8;
                    ldmx2(st + (uint32_t)((256 + rowW)*72 + kcolW)*2u, bh);
                    ldmx2(st + (uint32_t)((264 + rowW)*72 + kcolW)*2u, bl);
                    int rowA = w*16 + (lane & 7) + ((lane >> 3) & 1)*8;
                    int kcolA = kk16 + ((lane >> 4) & 1)*8;
                    uint32_t ah[4], al[4];
                    ldmx4(st + (uint32_t)(rowA*72 + kcolA)*2u, ah);
                    ldmx4(st + (uint32_t)((128 + rowA)*72 + kcolA)*2u, al);
                    mma16816(acm, ah, bh);
                    mma16816(acm, al, bh);
                    mma16816(acm, ah, bl);
                }
                __syncthreads();
            }
#pragma unroll
            for (int r = 0; r < 4; r++) {
                int row = w*16 + g2 + (r >> 1)*8;
                int gc = nb8 + q2 + (r & 1);
                float bb = (gc < 100) ? ba_[gc] : 0.f;
                g_akey[row*112 + gc] = tanhf(acm[r] + bb);
            }
        }
        grid_sync(&g_bar2, target += 128);

        // phase A2: softmax + context for batch myb
        {
            if (t < 112) s_ak[t] = g_akey[myb*112 + t];
            __syncthreads();
            float ex = 0.f;
            if (t < 128) {
                int L = lens[myb];
                const float* qk = g_qkey + ((int64_t)myb*S_SRC + t)*112;
                float pp = 0.f;
#pragma unroll 4
                for (int d = 0; d < 100; d++) pp = fmaf(qk[d], s_ak[d], pp);
                float e = (t < L) ? pp : -1e9f;
                float mx = e;
                for (int o = 16; o; o >>= 1) mx = fmaxf(mx, __shfl_xor_sync(0xffffffffu, mx, o));
                if (lane == 0) s_red[w] = mx;
                s_en[t] = e;
            }
            __syncthreads();
            if (t < 128) {
                float mx = fmaxf(fmaxf(s_red[0], s_red[1]), fmaxf(s_red[2], s_red[3]));
                ex = expf(s_en[t] - mx);
                float sm = ex;
                for (int o = 16; o; o >>= 1) sm += __shfl_xor_sync(0xffffffffu, sm, o);
                if (lane == 0) s_red[4 + w] = sm;
            }
            __syncthreads();
            if (t < 128) s_en[t] = ex;
            __syncthreads();
            float denom = s_red[4] + s_red[5] + s_red[6] + s_red[7];
            for (int d = t; d < 300; d += 256) {
                float c = 0.f;
#pragma unroll 4
                for (int s2 = 0; s2 < S_SRC; s2++)
                    c = fmaf(s_en[s2], g_qval[((int64_t)myb*S_SRC + s2)*304 + d], c);
                c /= denom;
                __nv_bfloat16 hv = __float2bfloat16(c);
                dAh[(int64_t)myb*KDR + 1024 + d] = hv;
                dAl[(int64_t)myb*KDR + 1024 + d] = __float2bfloat16(c - __bfloat162float(hv));
            }
        }
        grid_sync(&g_bar2, target += 128);

        // phase B: recurrent GEMM + LSTM epilogue
        {
            const float* add = g_decpre + (int64_t)ts*B*4096;
            float acc[2][2][4];
#pragma unroll
            for (int a = 0; a < 2; a++)
#pragma unroll
                for (int b2 = 0; b2 < 2; b2++)
#pragma unroll
                    for (int r = 0; r < 4; r++) acc[a][b2][r] = 0.f;

            gemm_phase<DCH>(smW, smS, t, lane, wm, wn, dAh, dAl, KDR, g_WdrL, KDR, nbase, acc);

            float* zb = (float*)(smraw + DCH*32*72*2);
#pragma unroll
            for (int mf = 0; mf < 2; mf++)
#pragma unroll
                for (int nf = 0; nf < 2; nf++)
#pragma unroll
                    for (int r = 0; r < 4; r++) {
                        int row = wm*32 + mf*16 + g2 + (r >> 1)*8;
                        int col = wn*16 + nf*8 + q2 + (r & 1);
                        zb[row*33 + col] = acc[mf][nf][r];
                    }
            __syncthreads();

            const int b = t & 127;
            const int jj0 = (t >> 7)*4;
#pragma unroll
            for (int jj = jj0; jj < jj0 + 4; jj++) {
                int jglob = (nbase >> 2) + jj;
                float4 pre = *(const float4*)&add[(int64_t)b*4096 + nbase + jj*4];
                float zi = zb[b*33 + jj*4 + 0] + pre.x + biasv[jglob];
                float zf = zb[b*33 + jj*4 + 1] + pre.y + biasv[1024 + jglob];
                float zg = zb[b*33 + jj*4 + 2] + pre.z + biasv[2048 + jglob];
                float zo = zb[b*33 + jj*4 + 3] + pre.w + biasv[3072 + jglob];
                float cold = g_dc[b*H + jglob];
                float si = 1.f/(1.f + expf(-zi));
                float sf = 1.f/(1.f + expf(-zf));
                float so = 1.f/(1.f + expf(-zo));
                float c2 = sf*cold + si*tanhf(zg);
                float h2 = so*tanhf(c2);
                g_dc[b*H + jglob] = c2;
                __nv_bfloat16 nh = __float2bfloat16(h2);
                __nv_bfloat16 nl = __float2bfloat16(h2 - __bfloat162float(nh));
                nAh[(int64_t)b*KDR + jglob] = nh;
                nAl[(int64_t)b*KDR + jglob] = nl;
                outF[((int64_t)b*S_TRG + ts)*H + jglob] = h2;
            }
        }
        grid_sync(&g_bar2, target += 128);
    }
}

// ---------------- one-shot GEMM (setup / batched ops) ----------------
__device__ __forceinline__ void load_chunk_g(uint32_t smb, int buf, int t, int k0,
    const __nv_bfloat16* __restrict__ Ah, const __nv_bfloat16* __restrict__ Al, int ldA, int mbase,
    const __nv_bfloat16* __restrict__ Wh, const __nv_bfloat16* __restrict__ Wl, int ldW, int nbase)
{
#pragma unroll
    for (int i = 0; i < 8; i++) {
        int u = i*256 + t;
        int hl = u >> 10, rem = u & 1023;
        int row = rem >> 3, grp = rem & 7;
        const __nv_bfloat16* src = (hl ? Al : Ah) + (int64_t)(mbase + row)*ldA + k0 + grp*8;
        cpa16(smb + (uint32_t)(((buf*2 + hl)*128 + row)*72 + grp*8)*2u, src);
    }
#pragma unroll
    for (int i = 0; i < 2; i++) {
        int u = i*256 + t;
        int hl = u >> 8, rem = u & 255;
        int row = rem >> 3, grp = rem & 7;
        const __nv_bfloat16* src = (hl ? Wl : Wh) + (int64_t)(nbase + row)*ldW + k0 + grp*8;
        cpa16(smb + (uint32_t)(36864 + ((buf*2 + hl)*32 + row)*72 + grp*8)*2u, src);
    }
    CP_COMMIT;
}

template<int OUT, int ACT>   // OUT: 0 fp32, 1 bf16 hi/lo ; ACT: 0 none, 1 relu, 2 tanh
__global__ __launch_bounds__(256) void mma_gemm(
    const __nv_bfloat16* __restrict__ Ah, const __nv_bfloat16* __restrict__ Al, int ldA,
    const __nv_bfloat16* __restrict__ Wh, const __nv_bfloat16* __restrict__ Wl, int ldW,
    int N, int KT, const float* __restrict__ bias,
    float* __restrict__ Cf, __nv_bfloat16* __restrict__ Ch, __nv_bfloat16* __restrict__ Cl, int ldC)
{
    extern __shared__ char smraw[];
    uint32_t smb = (uint32_t)__cvta_generic_to_shared(smraw);
    const int t = threadIdx.x;
    const int lane = t & 31, w = t >> 5;
    const int wm = w & 3, wn = w >> 2;
    const int mbase = blockIdx.y*128;
    const int nbase = blockIdx.x*32;

    float acc[2][2][4];
#pragma unroll
    for (int a = 0; a < 2; a++)
#pragma unroll
        for (int b2 = 0; b2 < 2; b2++)
#pragma unroll
            for (int r = 0; r < 4; r++) acc[a][b2][r] = 0.f;

    load_chunk_g(smb, 0, t, 0, Ah, Al, ldA, mbase, Wh, Wl, ldW, nbase);

    for (int kc = 0; kc < KT; kc++) {
        const int cur = kc & 1;
        if (kc + 1 < KT) {
            load_chunk_g(smb, cur ^ 1, t, (kc+1)*64, Ah, Al, ldA, mbase, Wh, Wl, ldW, nbase);
            CP_WAIT1;
        } else { CP_WAIT0; }
        __syncthreads();
#pragma unroll
        for (int kk16 = 0; kk16 < 64; kk16 += 16) {
            uint32_t bh[2][2], bl[2][2];
#pragma unroll
            for (int nf = 0; nf < 2; nf++) {
                int rowW = wn*16 + nf*8 + (lane & 7);
                int kcol = kk16 + ((lane >> 3) & 1)*8;
                ldmx2(smb + (uint32_t)(36864 + ((cur*2+0)*32 + rowW)*72 + kcol)*2u, bh[nf]);
                ldmx2(smb + (uint32_t)(36864 + ((cur*2+1)*32 + rowW)*72 + kcol)*2u, bl[nf]);
            }
#pragma unroll
            for (int mf = 0; mf < 2; mf++) {
                int rowA = wm*32 + mf*16 + (lane & 7) + ((lane >> 3) & 1)*8;
                int kcol = kk16 + ((lane >> 4) & 1)*8;
                uint32_t ah[4], al[4];
                ldmx4(smb + (uint32_t)(((cur*2+0)*128 + rowA)*72 + kcol)*2u, ah);
                ldmx4(smb + (uint32_t)(((cur*2+1)*128 + rowA)*72 + kcol)*2u, al);
#pragma unroll
                for (int nf = 0; nf < 2; nf++) {
                    mma16816(acc[mf][nf], ah, bh[nf]);
                    mma16816(acc[mf][nf], al, bh[nf]);
                    mma16816(acc[mf][nf], ah, bl[nf]);
                }
            }
        }
        __syncthreads();
    }

    const int g2 = lane >> 2, q2 = (lane & 3)*2;
#pragma unroll
    for (int mf = 0; mf < 2; mf++)
#pragma unroll
        for (int nf = 0; nf < 2; nf++)
#pragma unroll
            for (int r = 0; r < 4; r++) {
                int row = mbase + wm*32 + mf*16 + g2 + (r >> 1)*8;
                int col = nbase + wn*16 + nf*8 + q2 + (r & 1);
                if (col < N) {
                    float v = acc[mf][nf][r];
                    if (bias) v += bias[col];
                    if (ACT == 1) v = fmaxf(v, 0.f);
                    if (ACT == 2) v = tanhf(v);
                    if (OUT == 0) Cf[(int64_t)row*ldC + col] = v;
                    else {
                        __nv_bfloat16 hv = __float2bfloat16(v);
                        Ch[(int64_t)row*ldC + col] = hv;
                        Cl[(int64_t)row*ldC + col] = __float2bfloat16(v - __bfloat162float(hv));
                    }
                }
            }
}

// ---------------- launcher ----------------
#define GSA(p, s) cudaGetSymbolAddress((void**)&p, s)

extern "C" void kernel_launch(void* const* d_in, const int* in_sizes, int n_in,
                              void* d_out, int out_size) {
    const int*   src_seqs = (const int*)d_in[0];
    const int*   src_len  = (const int*)d_in[1];
    const int*   trg_nt   = (const int*)d_in[2];
    const int*   par_nt   = (const int*)d_in[3];
    const int*   par_lex  = (const int*)d_in[4];
    const float* lex_emb  = (const float*)d_in[5];
    const float* nt_emb   = (const float*)d_in[6];
    const float* enc_Wih  = (const float*)d_in[7];
    const float* enc_Whh  = (const float*)d_in[8];
    const float* enc_b    = (const float*)d_in[9];
    const float* dec_Wih  = (const float*)d_in[10];
    const float* dec_Whh  = (const float*)d_in[11];
    const float* dec_b    = (const float*)d_in[12];
    const float* Wh1 = (const float*)d_in[13];
    const float* bh1 = (const float*)d_in[14];
    const float* Wh2 = (const float*)d_in[15];
    const float* bh2 = (const float*)d_in[16];
    const float* Wc1 = (const float*)d_in[17];
    const float* bc1 = (const float*)d_in[18];
    const float* Wc2 = (const float*)d_in[19];
    const float* bc2 = (const float*)d_in[20];
    const float* Wa  = (const float*)d_in[21];
    const float* ba  = (const float*)d_in[22];
    const float* Wqk = (const float*)d_in[23];
    const float* bqk = (const float*)d_in[24];
    const float* Wqv = (const float*)d_in[25];
    const float* bqv = (const float*)d_in[26];
    float* out = (float*)d_out;

    cudaFuncSetAttribute(mma_gemm<0,0>, cudaFuncAttributeMaxDynamicSharedMemorySize, GEN_SMEM);
    cudaFuncSetAttribute(mma_gemm<0,2>, cudaFuncAttributeMaxDynamicSharedMemorySize, GEN_SMEM);
    cudaFuncSetAttribute(mma_gemm<1,0>, cudaFuncAttributeMaxDynamicSharedMemorySize, GEN_SMEM);
    cudaFuncSetAttribute(mma_gemm<1,1>, cudaFuncAttributeMaxDynamicSharedMemorySize, GEN_SMEM);
    cudaFuncSetAttribute(enc_persist, cudaFuncAttributeMaxDynamicSharedMemorySize, ENC_SMEM);
    cudaFuncSetAttribute(dec_persist, cudaFuncAttributeMaxDynamicSharedMemorySize, DEC_SMEM);

    __nv_bfloat16 *WerH,*WerL,*WdrH,*WdrL,*WeiH,*WeiL,*WdiH,*WdiL;
    __nv_bfloat16 *WqkH,*WqkL,*WqvH,*WqvL,*WaH,*WaL;
    __nv_bfloat16 *Wh1H,*Wh1L,*Wh2H,*Wh2L,*Wc1H,*Wc1L,*Wc2H,*Wc2L;
    __nv_bfloat16 *seH,*seL,*aeH,*aeL,*shH,*shL,*ehH,*ehL,*dAH,*dAL,*ecH,*ecL,*t1H,*t1L;
    float *encpre,*decpre,*qkey,*qval,*ec,*dc;
    GSA(WerH,g_WerH); GSA(WerL,g_WerL); GSA(WdrH,g_WdrH); GSA(WdrL,g_WdrL);
    GSA(WeiH,g_WeiH); GSA(WeiL,g_WeiL); GSA(WdiH,g_WdiH); GSA(WdiL,g_WdiL);
    GSA(WqkH,g_WqkH); GSA(WqkL,g_WqkL); GSA(WqvH,g_WqvH); GSA(WqvL,g_WqvL);
    GSA(WaH,g_WaH);   GSA(WaL,g_WaL);
    GSA(Wh1H,g_Wh1H); GSA(Wh1L,g_Wh1L); GSA(Wh2H,g_Wh2H); GSA(Wh2L,g_Wh2L);
    GSA(Wc1H,g_Wc1H); GSA(Wc1L,g_Wc1L); GSA(Wc2H,g_Wc2H); GSA(Wc2L,g_Wc2L);
    GSA(seH,g_seH); GSA(seL,g_seL); GSA(aeH,g_aeH); GSA(aeL,g_aeL);
    GSA(shH,g_shH); GSA(shL,g_shL); GSA(ehH,g_ehH); GSA(ehL,g_ehL);
    GSA(dAH,g_dAH); GSA(dAL,g_dAL); GSA(ecH,g_ecH); GSA(ecL,g_ecL);
    GSA(t1H,g_t1H); GSA(t1L,g_t1L);
    GSA(encpre,g_encpre); GSA(decpre,g_decpre);
    GSA(qkey,g_qkey); GSA(qval,g_qval); GSA(ec,g_ec); GSA(dc,g_dc);

    // setup
    convw_kernel<<<1024, 256>>>(WerH, WerL, enc_Whh, nullptr, 4096, 0, KE, 1024, 1024, 1);
    convw_kernel<<<1024, 256>>>(WdrH, WdrL, dec_Whh, dec_Wih, 4096, 0, KDR, 1324, 0, 2);
    convw_kernel<<<1024, 256>>>(WeiH, WeiL, enc_Wih, nullptr, 4096, 0, KSE, 300, 300, 1);
    convw_kernel<<<1024, 256>>>(WdiH, WdiL, dec_Wih, nullptr, 4096, 0, KAE, 556, 856, 1);
    convw_kernel<<<256, 256>>>(WqkH, WqkL, Wqk, nullptr, 128, 100, 1024, 1024, 1024, 0);
    convw_kernel<<<256, 256>>>(WqvH, WqvL, Wqv, nullptr, 320, 300, 1024, 1024, 1024, 0);
    convw_kernel<<<256, 256>>>(WaH,  WaL,  Wa,  nullptr, 128, 100, 1024, 1024, 1024, 0);
    convw_kernel<<<1024, 256>>>(Wh1H, Wh1L, Wh1, nullptr, 2048, 2048, 1024, 1024, 1024, 0);
    convw_kernel<<<1024, 256>>>(Wh2H, Wh2L, Wh2, nullptr, 1024, 1024, 2048, 2048, 2048, 0);
    convw_kernel<<<1024, 256>>>(Wc1H, Wc1L, Wc1, nullptr, 2048, 2048, 1024, 1024, 1024, 0);
    convw_kernel<<<1024, 256>>>(Wc2H, Wc2L, Wc2, nullptr, 1024, 1024, 2048, 2048, 2048, 0);
    gather_kernel<<<2048, 256>>>(src_seqs, trg_nt, par_nt, par_lex, lex_emb, nt_emb);

    // input-side precompute
    mma_gemm<0,0><<<dim3(128,128), 256, GEN_SMEM>>>(seH, seL, KSE, WeiH, WeiL, KSE,
        4096, KSE/64, nullptr, encpre, nullptr, nullptr, 4096);
    mma_gemm<0,0><<<dim3(128,64), 256, GEN_SMEM>>>(aeH, aeL, KAE, WdiH, WdiL, KAE,
        4096, KAE/64, nullptr, decpre, nullptr, nullptr, 4096);

    // encoder (persistent)
    enc_persist<<<128, 256, ENC_SMEM>>>(enc_b, src_len);
    __nv_bfloat16* ehTH = ehH;   // S_SRC even -> final state in buffer 0
    __nv_bfloat16* ehTL = ehL;

    // attention keys/values
    mma_gemm<0,2><<<dim3(4,128), 256, GEN_SMEM>>>(shH, shL, H, WqkH, WqkL, 1024,
        100, 16, bqk, qkey, nullptr, nullptr, 112);
    mma_gemm<0,0><<<dim3(10,128), 256, GEN_SMEM>>>(shH, shL, H, WqvH, WqvL, 1024,
        300, 16, bqv, qval, nullptr, nullptr, 304);

    // decoder init MLPs
    convw_kernel<<<256, 256>>>(ecH, ecL, ec, nullptr, 128, 128, 1024, 1024, 1024, 0);
    mma_gemm<1,1><<<dim3(64,1), 256, GEN_SMEM>>>(ehTH, ehTL, H, Wh1H, Wh1L, 1024,
        2048, 16, bh1, nullptr, t1H, t1L, 2048);
    mma_gemm<1,0><<<dim3(32,1), 256, GEN_SMEM>>>(t1H, t1L, 2048, Wh2H, Wh2L, 2048,
        1024, 32, bh2, nullptr, dAH, dAL, KDR);
    mma_gemm<1,1><<<dim3(64,1), 256, GEN_SMEM>>>(ecH, ecL, H, Wc1H, Wc1L, 1024,
        2048, 16, bc1, nullptr, t1H, t1L, 2048);
    mma_gemm<0,0><<<dim3(32,1), 256, GEN_SMEM>>>(t1H, t1L, 2048, Wc2H, Wc2L, 2048,
        1024, 32, bc2, dc, nullptr, nullptr, 1024);

    // decoder (persistent, attention fused)
    dec_persist<<<128, 256, DEC_SMEM>>>(dec_b, ba, src_len, out);
}